// round 3
// baseline (speedup 1.0000x reference)
#include <cuda_runtime.h>
#include <cfloat>
#include <cstdint>
#include <cstddef>

#define B_  65536
#define E_  384
#define H_  512
#define KC_ 256
#define Q_  4

// ---------------- scratch (static device globals; referenced directly from device code) ----------------
__device__ float g_scratch[(size_t)B_ * H_];   // enc hidden -> VQ scores -> dec hidden
__device__ float g_z[(size_t)B_ * H_];         // encoder output z
__device__ float g_res[(size_t)B_ * H_];       // running residual
__device__ float g_cbnorm[Q_ * KC_];           // ||cb_qk||^2
__device__ float g_commit_part[Q_ * (B_ / 8)];           // per-block commit partials
__device__ float g_recon_part[(B_ / 128) * (E_ / 128)];  // per-block recon partials

// which scratch buffer a GEMM reads/writes
enum Buf { BUF_EXT = 0, BUF_SCRATCH = 1, BUF_Z = 2, BUF_RES = 3 };

__device__ __forceinline__ float* buf_ptr(int b, const float* ext) {
    switch (b) {
        case BUF_SCRATCH: return g_scratch;
        case BUF_Z:       return g_z;
        case BUF_RES:     return g_res;
        default:          return (float*)ext;
    }
}

// ---------------- codebook norms: one warp per code ----------------
__global__ void cbnorm_kernel(const float* __restrict__ cb) {
    int warp = (blockIdx.x * blockDim.x + threadIdx.x) >> 5;
    int lane = threadIdx.x & 31;
    if (warp >= Q_ * KC_) return;
    const float* v = cb + (size_t)warp * H_;
    float s = 0.f;
    for (int i = lane; i < H_; i += 32) s = fmaf(v[i], v[i], s);
    #pragma unroll
    for (int o = 16; o; o >>= 1) s += __shfl_down_sync(0xffffffffu, s, o);
    if (lane == 0) g_cbnorm[warp] = s;
}

// ---------------- generic fp32 GEMM: C = act( (A - A2?) @ W(+T) + bias ) ----------------
// BM=BN=128, BK=8, 256 threads, 8x8 per thread.
// A is selected by ABUF (ext pointer or device global); C by CBUF. SUBA2 subtracts g_res from g_z.
template<bool RELU, bool TRANSB, bool LOSS, bool SUBA2, bool HASBIAS, int ABUF, int CBUF>
__global__ __launch_bounds__(256) void gemm_kernel(
    const float* __restrict__ Aext, const float* __restrict__ W,
    const float* __restrict__ bias, float* __restrict__ Cext,
    const float* __restrict__ Xc, int M, int N, int K)
{
    __shared__ float As[8][132];
    __shared__ float Ws[8][132];

    const float* A = buf_ptr(ABUF, Aext);
    float*       C = (CBUF == BUF_EXT) ? Cext : buf_ptr(CBUF, nullptr);

    const int tid = threadIdx.x;
    const int m0 = blockIdx.y * 128;
    const int n0 = blockIdx.x * 128;

    const int ar = tid >> 1;          // A tile row 0..127
    const int ac = (tid & 1) * 4;     // A tile k offset 0/4
    const int wr = tid >> 5;          // W (normal): k 0..7
    const int wc = (tid & 31) * 4;    // W (normal): n offset
    const int tr = tid >> 1;          // W (TRANSB): n 0..127
    const int tc = (tid & 1) * 4;     // W (TRANSB): k offset

    const int tx = tid & 15;
    const int ty = tid >> 4;

    float acc[8][8];
    #pragma unroll
    for (int i = 0; i < 8; i++)
        #pragma unroll
        for (int j = 0; j < 8; j++) acc[i][j] = 0.f;

    for (int k0 = 0; k0 < K; k0 += 8) {
        float4 av = *(const float4*)(A + (size_t)(m0 + ar) * K + k0 + ac);
        if (SUBA2) {
            float4 bv = *(const float4*)(g_res + (size_t)(m0 + ar) * K + k0 + ac);
            av.x -= bv.x; av.y -= bv.y; av.z -= bv.z; av.w -= bv.w;
        }
        As[ac + 0][ar] = av.x; As[ac + 1][ar] = av.y;
        As[ac + 2][ar] = av.z; As[ac + 3][ar] = av.w;

        if (TRANSB) {
            float4 wv = *(const float4*)(W + (size_t)(n0 + tr) * K + k0 + tc);
            Ws[tc + 0][tr] = wv.x; Ws[tc + 1][tr] = wv.y;
            Ws[tc + 2][tr] = wv.z; Ws[tc + 3][tr] = wv.w;
        } else {
            float4 wv = *(const float4*)(W + (size_t)(k0 + wr) * N + n0 + wc);
            *(float4*)&Ws[wr][wc] = wv;
        }
        __syncthreads();

        #pragma unroll
        for (int kk = 0; kk < 8; kk++) {
            float areg[8], breg[8];
            #pragma unroll
            for (int i = 0; i < 8; i++) areg[i] = As[kk][ty * 8 + i];
            #pragma unroll
            for (int j = 0; j < 8; j++) breg[j] = Ws[kk][tx * 8 + j];
            #pragma unroll
            for (int i = 0; i < 8; i++)
                #pragma unroll
                for (int j = 0; j < 8; j++)
                    acc[i][j] = fmaf(areg[i], breg[j], acc[i][j]);
        }
        __syncthreads();
    }

    float lsum = 0.f;
    #pragma unroll
    for (int i = 0; i < 8; i++) {
        const int row = m0 + ty * 8 + i;
        #pragma unroll
        for (int j = 0; j < 8; j++) {
            const int col = n0 + tx * 8 + j;
            float v = acc[i][j];
            if (HASBIAS) v += __ldg(bias + col);
            if (RELU) v = fmaxf(v, 0.f);
            C[(size_t)row * N + col] = v;
            if (LOSS) {
                float d = v - __ldg(Xc + (size_t)row * N + col);
                lsum = fmaf(d, d, lsum);
            }
        }
    }
    if (LOSS) {
        #pragma unroll
        for (int o = 16; o; o >>= 1) lsum += __shfl_down_sync(0xffffffffu, lsum, o);
        __shared__ float red[8];
        if ((tid & 31) == 0) red[tid >> 5] = lsum;
        __syncthreads();
        if (tid == 0) {
            float t = 0.f;
            #pragma unroll
            for (int i = 0; i < 8; i++) t += red[i];
            g_recon_part[blockIdx.y * gridDim.x + blockIdx.x] = t;
        }
    }
}

// ---------------- residual = z (copy) ----------------
__global__ void copy_kernel() {
    size_t n4 = (size_t)B_ * H_ / 4;
    size_t i = (size_t)blockIdx.x * blockDim.x + threadIdx.x;
    size_t stride = (size_t)gridDim.x * blockDim.x;
    const float4* s = (const float4*)g_z;
    float4* d = (float4*)g_res;
    for (; i < n4; i += stride) d[i] = s[i];
}

// ---------------- per-level argmin + residual update + commit partial ----------------
// 256 threads = 8 warps = 8 rows per block. Reference-exact earliest-min tie-break.
__global__ __launch_bounds__(256) void argmin_update_kernel(
    int q, const float* __restrict__ cb, float* __restrict__ idx_out, int write_idx)
{
    const int warp = threadIdx.x >> 5;
    const int lane = threadIdx.x & 31;
    const int row = blockIdx.x * 8 + warp;

    const float* srow = g_scratch + (size_t)row * KC_;
    float best = FLT_MAX;
    int bidx = KC_;
    #pragma unroll
    for (int k0 = 0; k0 < KC_; k0 += 32) {
        int k = k0 + lane;
        float d = g_cbnorm[q * KC_ + k] - 2.0f * srow[k];
        if (d < best) { best = d; bidx = k; }   // strict '<' keeps earliest k per lane
    }
    #pragma unroll
    for (int o = 16; o; o >>= 1) {
        float ob = __shfl_down_sync(0xffffffffu, best, o);
        int   oi = __shfl_down_sync(0xffffffffu, bidx, o);
        if (ob < best || (ob == best && oi < bidx)) { best = ob; bidx = oi; }
    }
    bidx = __shfl_sync(0xffffffffu, bidx, 0);

    if (write_idx && lane == 0)
        idx_out[(size_t)row * Q_ + q] = (float)bidx;

    const float* cv = cb + ((size_t)q * KC_ + bidx) * H_;
    float* rrow = g_res + (size_t)row * H_;
    float cs = 0.f;
    #pragma unroll
    for (int p = lane * 4; p < H_; p += 128) {
        float4 r = *(const float4*)(rrow + p);
        float4 c = *(const float4*)(cv + p);
        r.x -= c.x; r.y -= c.y; r.z -= c.z; r.w -= c.w;
        *(float4*)(rrow + p) = r;
        cs += r.x * r.x + r.y * r.y + r.z * r.z + r.w * r.w;
    }
    #pragma unroll
    for (int o = 16; o; o >>= 1) cs += __shfl_down_sync(0xffffffffu, cs, o);

    __shared__ float wsum[8];
    if (lane == 0) wsum[warp] = cs;
    __syncthreads();
    if (threadIdx.x == 0) {
        float t = 0.f;
        #pragma unroll
        for (int i = 0; i < 8; i++) t += wsum[i];
        g_commit_part[(size_t)q * (B_ / 8) + blockIdx.x] = t;
    }
}

// ---------------- final scalar reduction ----------------
__global__ void finalize_kernel(float* __restrict__ out) {
    __shared__ double sc[256], sr[256];
    double c = 0.0, r = 0.0;
    for (int i = threadIdx.x; i < Q_ * (B_ / 8); i += 256) c += (double)g_commit_part[i];
    for (int i = threadIdx.x; i < (B_ / 128) * (E_ / 128); i += 256) r += (double)g_recon_part[i];
    sc[threadIdx.x] = c; sr[threadIdx.x] = r;
    __syncthreads();
    for (int s = 128; s; s >>= 1) {
        if (threadIdx.x < s) { sc[threadIdx.x] += sc[threadIdx.x + s]; sr[threadIdx.x] += sr[threadIdx.x + s]; }
        __syncthreads();
    }
    if (threadIdx.x == 0) {
        out[(size_t)B_ * E_ + (size_t)B_ * Q_ + 0] = (float)(sr[0] / ((double)B_ * (double)E_));
        out[(size_t)B_ * E_ + (size_t)B_ * Q_ + 1] = (float)(0.25 * sc[0] / ((double)B_ * (double)H_));
    }
}

// ---------------- launch: kernel launches ONLY ----------------
extern "C" void kernel_launch(void* const* d_in, const int* in_sizes, int n_in,
                              void* d_out, int out_size) {
    const float* x   = (const float*)d_in[0];
    const float* We1 = (const float*)d_in[1];
    const float* be1 = (const float*)d_in[2];
    const float* We2 = (const float*)d_in[3];
    const float* be2 = (const float*)d_in[4];
    const float* Wd1 = (const float*)d_in[5];
    const float* bd1 = (const float*)d_in[6];
    const float* Wd2 = (const float*)d_in[7];
    const float* bd2 = (const float*)d_in[8];
    const float* cb  = (const float*)d_in[9];
    float* out = (float*)d_out;

    // Output layout assumption: [reconstructed (B*E) | indices-as-float (B*Q) | recon_loss | commit_loss]
    const int full = out_size >= (int)((size_t)B_ * E_ + (size_t)B_ * Q_ + 2);
    float* idx_out = out + (size_t)B_ * E_;

    dim3 blk(256);

    cbnorm_kernel<<<(Q_ * KC_) / 8, 256>>>(cb);

    // enc1: scratch = relu(x @ We1 + be1)      [B,384]x[384,512]
    gemm_kernel<true,  false, false, false, true,  BUF_EXT,     BUF_SCRATCH>
        <<<dim3(H_ / 128, B_ / 128), blk>>>(x, We1, be1, nullptr, nullptr, B_, H_, E_);
    // enc2: z = scratch @ We2 + be2            [B,512]x[512,512]
    gemm_kernel<false, false, false, false, true,  BUF_SCRATCH, BUF_Z>
        <<<dim3(H_ / 128, B_ / 128), blk>>>(nullptr, We2, be2, nullptr, nullptr, B_, H_, H_);

    // residual = z
    copy_kernel<<<2048, 256>>>();

    // residual VQ: 4 levels of (scores GEMM -> argmin + residual update)
    for (int q = 0; q < Q_; q++) {
        gemm_kernel<false, true, false, false, false, BUF_RES, BUF_SCRATCH>
            <<<dim3(KC_ / 128, B_ / 128), blk>>>(nullptr, cb + (size_t)q * KC_ * H_,
                                                 nullptr, nullptr, nullptr, B_, KC_, H_);
        argmin_update_kernel<<<B_ / 8, 256>>>(q, cb, idx_out, full);
    }

    // dec1: scratch = relu((z - res) @ Wd1 + bd1)   (quantized = z - residual_final)
    gemm_kernel<true,  false, false, true,  true,  BUF_Z,       BUF_SCRATCH>
        <<<dim3(H_ / 128, B_ / 128), blk>>>(nullptr, Wd1, bd1, nullptr, nullptr, B_, H_, H_);
    // dec2: out = scratch @ Wd2 + bd2, fused recon-loss partials vs x
    gemm_kernel<false, false, true,  false, true,  BUF_SCRATCH, BUF_EXT>
        <<<dim3(E_ / 128, B_ / 128), blk>>>(nullptr, Wd2, bd2, out, x, B_, E_, H_);

    if (full) finalize_kernel<<<1, 256>>>(out);
}

// round 4
// speedup vs baseline: 1.0007x; 1.0007x over previous
#include <cuda_runtime.h>
#include <cfloat>
#include <cstdint>
#include <cstddef>

#define B_  65536
#define E_  384
#define H_  512
#define KC_ 256
#define Q_  4

// ---------------- scratch (static device globals; referenced directly from device code) ----------------
__device__ float g_scratch[(size_t)B_ * H_];   // enc hidden -> VQ scores -> dec hidden
__device__ float g_z[(size_t)B_ * H_];         // encoder output z
__device__ float g_res[(size_t)B_ * H_];       // running residual
__device__ float g_cbnorm[Q_ * KC_];           // ||cb_qk||^2
__device__ float g_commit_part[Q_ * (B_ / 8)];           // per-block commit partials
__device__ float g_recon_part[(B_ / 128) * (E_ / 128)];  // per-block recon partials

// which scratch buffer a GEMM reads/writes
enum Buf { BUF_EXT = 0, BUF_SCRATCH = 1, BUF_Z = 2, BUF_RES = 3 };

__device__ __forceinline__ float* buf_ptr(int b, const float* ext) {
    switch (b) {
        case BUF_SCRATCH: return g_scratch;
        case BUF_Z:       return g_z;
        case BUF_RES:     return g_res;
        default:          return (float*)ext;
    }
}

// ---------------- codebook norms: one warp per code ----------------
__global__ void cbnorm_kernel(const float* __restrict__ cb) {
    int warp = (blockIdx.x * blockDim.x + threadIdx.x) >> 5;
    int lane = threadIdx.x & 31;
    if (warp >= Q_ * KC_) return;
    const float* v = cb + (size_t)warp * H_;
    float s = 0.f;
    for (int i = lane; i < H_; i += 32) s = fmaf(v[i], v[i], s);
    #pragma unroll
    for (int o = 16; o; o >>= 1) s += __shfl_down_sync(0xffffffffu, s, o);
    if (lane == 0) g_cbnorm[warp] = s;
}

// ---------------- generic fp32 GEMM: C = act( (A - A2?) @ W(+T) + bias ) ----------------
// BM=BN=128, BK=8, 256 threads, 8x8 per thread.
// A is selected by ABUF (ext pointer or device global); C by CBUF. SUBA2 subtracts g_res from g_z.
template<bool RELU, bool TRANSB, bool LOSS, bool SUBA2, bool HASBIAS, int ABUF, int CBUF>
__global__ __launch_bounds__(256) void gemm_kernel(
    const float* __restrict__ Aext, const float* __restrict__ W,
    const float* __restrict__ bias, float* __restrict__ Cext,
    const float* __restrict__ Xc, int M, int N, int K)
{
    __shared__ float As[8][132];
    __shared__ float Ws[8][132];

    const float* A = buf_ptr(ABUF, Aext);
    float*       C = (CBUF == BUF_EXT) ? Cext : buf_ptr(CBUF, nullptr);

    const int tid = threadIdx.x;
    const int m0 = blockIdx.y * 128;
    const int n0 = blockIdx.x * 128;

    const int ar = tid >> 1;          // A tile row 0..127
    const int ac = (tid & 1) * 4;     // A tile k offset 0/4
    const int wr = tid >> 5;          // W (normal): k 0..7
    const int wc = (tid & 31) * 4;    // W (normal): n offset
    const int tr = tid >> 1;          // W (TRANSB): n 0..127
    const int tc = (tid & 1) * 4;     // W (TRANSB): k offset

    const int tx = tid & 15;
    const int ty = tid >> 4;

    float acc[8][8];
    #pragma unroll
    for (int i = 0; i < 8; i++)
        #pragma unroll
        for (int j = 0; j < 8; j++) acc[i][j] = 0.f;

    for (int k0 = 0; k0 < K; k0 += 8) {
        float4 av = *(const float4*)(A + (size_t)(m0 + ar) * K + k0 + ac);
        if (SUBA2) {
            float4 bv = *(const float4*)(g_res + (size_t)(m0 + ar) * K + k0 + ac);
            av.x -= bv.x; av.y -= bv.y; av.z -= bv.z; av.w -= bv.w;
        }
        As[ac + 0][ar] = av.x; As[ac + 1][ar] = av.y;
        As[ac + 2][ar] = av.z; As[ac + 3][ar] = av.w;

        if (TRANSB) {
            float4 wv = *(const float4*)(W + (size_t)(n0 + tr) * K + k0 + tc);
            Ws[tc + 0][tr] = wv.x; Ws[tc + 1][tr] = wv.y;
            Ws[tc + 2][tr] = wv.z; Ws[tc + 3][tr] = wv.w;
        } else {
            float4 wv = *(const float4*)(W + (size_t)(k0 + wr) * N + n0 + wc);
            *(float4*)&Ws[wr][wc] = wv;
        }
        __syncthreads();

        #pragma unroll
        for (int kk = 0; kk < 8; kk++) {
            float areg[8], breg[8];
            #pragma unroll
            for (int i = 0; i < 8; i++) areg[i] = As[kk][ty * 8 + i];
            #pragma unroll
            for (int j = 0; j < 8; j++) breg[j] = Ws[kk][tx * 8 + j];
            #pragma unroll
            for (int i = 0; i < 8; i++)
                #pragma unroll
                for (int j = 0; j < 8; j++)
                    acc[i][j] = fmaf(areg[i], breg[j], acc[i][j]);
        }
        __syncthreads();
    }

    float lsum = 0.f;
    #pragma unroll
    for (int i = 0; i < 8; i++) {
        const int row = m0 + ty * 8 + i;
        #pragma unroll
        for (int j = 0; j < 8; j++) {
            const int col = n0 + tx * 8 + j;
            float v = acc[i][j];
            if (HASBIAS) v += __ldg(bias + col);
            if (RELU) v = fmaxf(v, 0.f);
            C[(size_t)row * N + col] = v;
            if (LOSS) {
                float d = v - __ldg(Xc + (size_t)row * N + col);
                lsum = fmaf(d, d, lsum);
            }
        }
    }
    if (LOSS) {
        #pragma unroll
        for (int o = 16; o; o >>= 1) lsum += __shfl_down_sync(0xffffffffu, lsum, o);
        __shared__ float red[8];
        if ((tid & 31) == 0) red[tid >> 5] = lsum;
        __syncthreads();
        if (tid == 0) {
            float t = 0.f;
            #pragma unroll
            for (int i = 0; i < 8; i++) t += red[i];
            g_recon_part[blockIdx.y * gridDim.x + blockIdx.x] = t;
        }
    }
}

// ---------------- residual = z (copy) ----------------
__global__ void copy_kernel() {
    size_t n4 = (size_t)B_ * H_ / 4;
    size_t i = (size_t)blockIdx.x * blockDim.x + threadIdx.x;
    size_t stride = (size_t)gridDim.x * blockDim.x;
    const float4* s = (const float4*)g_z;
    float4* d = (float4*)g_res;
    for (; i < n4; i += stride) d[i] = s[i];
}

// ---------------- per-level argmin + residual update + commit partial ----------------
// 256 threads = 8 warps = 8 rows per block. Reference-exact earliest-min tie-break.
__global__ __launch_bounds__(256) void argmin_update_kernel(
    int q, const float* __restrict__ cb, float* __restrict__ idx_out, int write_idx)
{
    const int warp = threadIdx.x >> 5;
    const int lane = threadIdx.x & 31;
    const int row = blockIdx.x * 8 + warp;

    const float* srow = g_scratch + (size_t)row * KC_;
    float best = FLT_MAX;
    int bidx = KC_;
    #pragma unroll
    for (int k0 = 0; k0 < KC_; k0 += 32) {
        int k = k0 + lane;
        float d = g_cbnorm[q * KC_ + k] - 2.0f * srow[k];
        if (d < best) { best = d; bidx = k; }   // strict '<' keeps earliest k per lane
    }
    #pragma unroll
    for (int o = 16; o; o >>= 1) {
        float ob = __shfl_down_sync(0xffffffffu, best, o);
        int   oi = __shfl_down_sync(0xffffffffu, bidx, o);
        if (ob < best || (ob == best && oi < bidx)) { best = ob; bidx = oi; }
    }
    bidx = __shfl_sync(0xffffffffu, bidx, 0);

    if (write_idx && lane == 0)
        idx_out[(size_t)row * Q_ + q] = (float)bidx;

    const float* cv = cb + ((size_t)q * KC_ + bidx) * H_;
    float* rrow = g_res + (size_t)row * H_;
    float cs = 0.f;
    #pragma unroll
    for (int p = lane * 4; p < H_; p += 128) {
        float4 r = *(const float4*)(rrow + p);
        float4 c = *(const float4*)(cv + p);
        r.x -= c.x; r.y -= c.y; r.z -= c.z; r.w -= c.w;
        *(float4*)(rrow + p) = r;
        cs += r.x * r.x + r.y * r.y + r.z * r.z + r.w * r.w;
    }
    #pragma unroll
    for (int o = 16; o; o >>= 1) cs += __shfl_down_sync(0xffffffffu, cs, o);

    __shared__ float wsum[8];
    if (lane == 0) wsum[warp] = cs;
    __syncthreads();
    if (threadIdx.x == 0) {
        float t = 0.f;
        #pragma unroll
        for (int i = 0; i < 8; i++) t += wsum[i];
        g_commit_part[(size_t)q * (B_ / 8) + blockIdx.x] = t;
    }
}

// ---------------- final scalar reduction ----------------
__global__ void finalize_kernel(float* __restrict__ out) {
    __shared__ double sc[256], sr[256];
    double c = 0.0, r = 0.0;
    for (int i = threadIdx.x; i < Q_ * (B_ / 8); i += 256) c += (double)g_commit_part[i];
    for (int i = threadIdx.x; i < (B_ / 128) * (E_ / 128); i += 256) r += (double)g_recon_part[i];
    sc[threadIdx.x] = c; sr[threadIdx.x] = r;
    __syncthreads();
    for (int s = 128; s; s >>= 1) {
        if (threadIdx.x < s) { sc[threadIdx.x] += sc[threadIdx.x + s]; sr[threadIdx.x] += sr[threadIdx.x + s]; }
        __syncthreads();
    }
    if (threadIdx.x == 0) {
        out[(size_t)B_ * E_ + (size_t)B_ * Q_ + 0] = (float)(sr[0] / ((double)B_ * (double)E_));
        out[(size_t)B_ * E_ + (size_t)B_ * Q_ + 1] = (float)(0.25 * sc[0] / ((double)B_ * (double)H_));
    }
}

// ---------------- launch: kernel launches ONLY ----------------
extern "C" void kernel_launch(void* const* d_in, const int* in_sizes, int n_in,
                              void* d_out, int out_size) {
    const float* x   = (const float*)d_in[0];
    const float* We1 = (const float*)d_in[1];
    const float* be1 = (const float*)d_in[2];
    const float* We2 = (const float*)d_in[3];
    const float* be2 = (const float*)d_in[4];
    const float* Wd1 = (const float*)d_in[5];
    const float* bd1 = (const float*)d_in[6];
    const float* Wd2 = (const float*)d_in[7];
    const float* bd2 = (const float*)d_in[8];
    const float* cb  = (const float*)d_in[9];
    float* out = (float*)d_out;

    // Output layout assumption: [reconstructed (B*E) | indices-as-float (B*Q) | recon_loss | commit_loss]
    const int full = out_size >= (int)((size_t)B_ * E_ + (size_t)B_ * Q_ + 2);
    float* idx_out = out + (size_t)B_ * E_;

    dim3 blk(256);

    cbnorm_kernel<<<(Q_ * KC_) / 8, 256>>>(cb);

    // enc1: scratch = relu(x @ We1 + be1)      [B,384]x[384,512]
    gemm_kernel<true,  false, false, false, true,  BUF_EXT,     BUF_SCRATCH>
        <<<dim3(H_ / 128, B_ / 128), blk>>>(x, We1, be1, nullptr, nullptr, B_, H_, E_);
    // enc2: z = scratch @ We2 + be2            [B,512]x[512,512]
    gemm_kernel<false, false, false, false, true,  BUF_SCRATCH, BUF_Z>
        <<<dim3(H_ / 128, B_ / 128), blk>>>(nullptr, We2, be2, nullptr, nullptr, B_, H_, H_);

    // residual = z
    copy_kernel<<<2048, 256>>>();

    // residual VQ: 4 levels of (scores GEMM -> argmin + residual update)
    for (int q = 0; q < Q_; q++) {
        gemm_kernel<false, true, false, false, false, BUF_RES, BUF_SCRATCH>
            <<<dim3(KC_ / 128, B_ / 128), blk>>>(nullptr, cb + (size_t)q * KC_ * H_,
                                                 nullptr, nullptr, nullptr, B_, KC_, H_);
        argmin_update_kernel<<<B_ / 8, 256>>>(q, cb, idx_out, full);
    }

    // dec1: scratch = relu((z - res) @ Wd1 + bd1)   (quantized = z - residual_final)
    gemm_kernel<true,  false, false, true,  true,  BUF_Z,       BUF_SCRATCH>
        <<<dim3(H_ / 128, B_ / 128), blk>>>(nullptr, Wd1, bd1, nullptr, nullptr, B_, H_, H_);
    // dec2: out = scratch @ Wd2 + bd2, fused recon-loss partials vs x
    gemm_kernel<false, false, true,  false, true,  BUF_SCRATCH, BUF_EXT>
        <<<dim3(E_ / 128, B_ / 128), blk>>>(nullptr, Wd2, bd2, out, x, B_, E_, H_);

    if (full) finalize_kernel<<<1, 256>>>(out);
}

// round 12
// speedup vs baseline: 1.4195x; 1.4186x over previous
#include <cuda_runtime.h>
#include <cuda_bf16.h>
#include <cstdint>
#include <cstddef>
#include <cfloat>

#define B_  65536
#define E_  384
#define H_  512
#define KC_ 256
#define Q_  4
#define EPS_CAND 0.25f

// ---------------- static device buffers ----------------
__device__ float g_scratch[(size_t)B_*H_];               // enc hidden (fp32)
__device__ float gZ[(size_t)B_*H_];                      // z (fp32 master)
__device__ float gR[(size_t)B_*H_];                      // residual (fp32 master)
__device__ __nv_bfloat16 gRc[2][(size_t)B_*H_];          // residual split planes (h,m)
__device__ __nv_bfloat16 gQc[2][(size_t)B_*H_];          // quantized split planes
__device__ __nv_bfloat16 gGc[2][(size_t)B_*H_];          // dec hidden split planes
__device__ __nv_bfloat16 gW3c[2][H_*H_];                 // Wd1^T planes [n][k]
__device__ __nv_bfloat16 gW4c[2][E_*H_];                 // Wd2^T planes [n][k]
__device__ __nv_bfloat16 gCBc[2][Q_*KC_*H_];             // codebook planes [code][k]
__device__ float g_cbnorm[Q_*KC_];
__device__ float g_commit[Q_*512];
__device__ float g_recon[3*512];

// ---------------- helpers ----------------
__device__ __forceinline__ uint32_t smem_u32(const void* p) {
    uint32_t a;
    asm("{ .reg .u64 t; cvta.to.shared.u64 t, %1; cvt.u32.u64 %0, t; }" : "=r"(a) : "l"(p));
    return a;
}
__device__ __forceinline__ void cp16(uint32_t s, const void* g) {
    asm volatile("{ .reg .u64 p; cvta.to.global.u64 p, %1; cp.async.cg.shared.global [%0], [p], 16; }"
                 :: "r"(s), "l"(g) : "memory");
}
#define CP_COMMIT() asm volatile("cp.async.commit_group;" ::: "memory")
__device__ __forceinline__ void cp_wait1() { asm volatile("cp.async.wait_group 1;" ::: "memory"); }
__device__ __forceinline__ void cp_wait0() { asm volatile("cp.async.wait_group 0;" ::: "memory"); }

__device__ __forceinline__ void ldm_x4(uint32_t* r, uint32_t a) {
    asm volatile("ldmatrix.sync.aligned.m8n8.x4.shared.b16 {%0,%1,%2,%3}, [%4];"
        : "=r"(r[0]), "=r"(r[1]), "=r"(r[2]), "=r"(r[3]) : "r"(a));
}
__device__ __forceinline__ void ldm_x2(uint32_t* r, uint32_t a) {
    asm volatile("ldmatrix.sync.aligned.m8n8.x2.shared.b16 {%0,%1}, [%2];"
        : "=r"(r[0]), "=r"(r[1]) : "r"(a));
}
__device__ __forceinline__ void mma16816(float* c, const uint32_t* a, const uint32_t* b) {
    asm volatile("mma.sync.aligned.m16n8k16.row.col.f32.bf16.bf16.f32 "
        "{%0,%1,%2,%3}, {%4,%5,%6,%7}, {%8,%9}, {%0,%1,%2,%3};"
        : "+f"(c[0]), "+f"(c[1]), "+f"(c[2]), "+f"(c[3])
        : "r"(a[0]), "r"(a[1]), "r"(a[2]), "r"(a[3]), "r"(b[0]), "r"(b[1]));
}
__device__ __forceinline__ void split2s(float a, float& h, float& m) {
    h = __bfloat162float(__float2bfloat16_rn(a));
    m = a - h;
}
__device__ __forceinline__ uint32_t bfpack(float lo, float hi) {
    __nv_bfloat162 p = __floats2bfloat162_rn(lo, hi);
    return *(uint32_t*)&p;
}

// ---------------- prep kernels ----------------
__global__ void prep_weights(const float* __restrict__ W3, const float* __restrict__ W4,
                             const float* __restrict__ cb) {
    size_t stride = (size_t)gridDim.x * blockDim.x;
    size_t i0 = (size_t)blockIdx.x*blockDim.x + threadIdx.x;
    for (size_t t = i0; t < (size_t)H_*H_; t += stride) {
        size_t n = t / H_, k = t % H_;
        float h, m; split2s(W3[k*H_ + n], h, m);
        gW3c[0][t] = __float2bfloat16_rn(h); gW3c[1][t] = __float2bfloat16_rn(m);
    }
    for (size_t t = i0; t < (size_t)E_*H_; t += stride) {
        size_t n = t / H_, k = t % H_;
        float h, m; split2s(W4[k*E_ + n], h, m);
        gW4c[0][t] = __float2bfloat16_rn(h); gW4c[1][t] = __float2bfloat16_rn(m);
    }
    for (size_t t = i0; t < (size_t)Q_*KC_*H_; t += stride) {
        float h, m; split2s(cb[t], h, m);
        gCBc[0][t] = __float2bfloat16_rn(h); gCBc[1][t] = __float2bfloat16_rn(m);
    }
}
__global__ void cbnorm_kernel(const float* __restrict__ cb) {
    int warp = (blockIdx.x*blockDim.x + threadIdx.x) >> 5;
    int lane = threadIdx.x & 31;
    if (warp >= Q_*KC_) return;
    const float* v = cb + (size_t)warp * H_;
    float s = 0.f;
    for (int i = lane; i < H_; i += 32) s = fmaf(v[i], v[i], s);
    #pragma unroll
    for (int o = 16; o; o >>= 1) s += __shfl_down_sync(0xffffffffu, s, o);
    if (lane == 0) g_cbnorm[warp] = s;
}

// ---------------- SIMT fp32 encoder GEMM (identical core to the proven R3 kernel) ----------------
// MODE 0: enc1  C = relu(x @ W1 + b1) -> g_scratch
// MODE 1: enc2  z = scratch @ W2 + b2 -> gZ, gR (fp32) + gRc split planes
template<bool RELU, int MODE>
__global__ __launch_bounds__(256) void genc(
    const float* __restrict__ Aext, const float* __restrict__ W,
    const float* __restrict__ bias, int M, int N, int K)
{
    __shared__ float As[8][132];
    __shared__ float Ws[8][132];

    const float* A = (MODE == 0) ? Aext : g_scratch;

    const int tid = threadIdx.x;
    const int m0 = blockIdx.y * 128;
    const int n0 = blockIdx.x * 128;

    const int ar = tid >> 1;
    const int ac = (tid & 1) * 4;
    const int wr = tid >> 5;
    const int wc = (tid & 31) * 4;
    const int tx = tid & 15;
    const int ty = tid >> 4;

    float acc[8][8];
    #pragma unroll
    for (int i = 0; i < 8; i++)
        #pragma unroll
        for (int j = 0; j < 8; j++) acc[i][j] = 0.f;

    for (int k0 = 0; k0 < K; k0 += 8) {
        float4 av = *(const float4*)(A + (size_t)(m0 + ar) * K + k0 + ac);
        As[ac + 0][ar] = av.x; As[ac + 1][ar] = av.y;
        As[ac + 2][ar] = av.z; As[ac + 3][ar] = av.w;
        float4 wv = *(const float4*)(W + (size_t)(k0 + wr) * N + n0 + wc);
        *(float4*)&Ws[wr][wc] = wv;
        __syncthreads();

        #pragma unroll
        for (int kk = 0; kk < 8; kk++) {
            float areg[8], breg[8];
            #pragma unroll
            for (int i = 0; i < 8; i++) areg[i] = As[kk][ty * 8 + i];
            #pragma unroll
            for (int j = 0; j < 8; j++) breg[j] = Ws[kk][tx * 8 + j];
            #pragma unroll
            for (int i = 0; i < 8; i++)
                #pragma unroll
                for (int j = 0; j < 8; j++)
                    acc[i][j] = fmaf(areg[i], breg[j], acc[i][j]);
        }
        __syncthreads();
    }

    #pragma unroll
    for (int i = 0; i < 8; i++) {
        const int row = m0 + ty * 8 + i;
        #pragma unroll
        for (int j = 0; j < 8; j++) {
            const int col = n0 + tx * 8 + j;
            float v = acc[i][j] + __ldg(bias + col);
            if (RELU) v = fmaxf(v, 0.f);
            size_t go = (size_t)row * N + col;
            if (MODE == 0) {
                g_scratch[go] = v;
            } else {
                gZ[go] = v; gR[go] = v;
                float h, m; split2s(v, h, m);
                gRc[0][go] = __float2bfloat16_rn(h);
                gRc[1][go] = __float2bfloat16_rn(m);
            }
        }
    }
}

// ---------------- plane selectors (tensor path) ----------------
template<int EPI> __device__ __forceinline__ const __nv_bfloat16* Apl(int c) {
    if (EPI == 2) return gRc[c];
    if (EPI == 3) return gQc[c];
    return gGc[c];
}
template<int EPI> __device__ __forceinline__ const __nv_bfloat16* Bpl(int c, int q) {
    if (EPI == 2) return gCBc[c] + (size_t)q*KC_*H_;
    if (EPI == 3) return gW3c[c];
    return gW4c[c];
}

// ---------------- tensor-core GEMM (3-term split) with fused epilogues ----------------
// EPI: 2=scores(candidate-exact argmin + residual update) 3=dec1(relu->gGc) 4=dec2(out+loss)
template<int EPI, int NT, int KCH>
__global__ __launch_bounds__(512, 1) void tc(
    int K, const float* __restrict__ bias,
    int q, const float* __restrict__ cbf, float* __restrict__ idx_out, int wq, int last,
    float* __restrict__ out, const float* __restrict__ xref)
{
    constexpr int NP   = 2;
    constexpr int SUM  = 1;
    constexpr int ROWB = KCH * 2;
    constexpr int WN   = NT / 8;
    constexpr int NF   = WN / 8;
    constexpr int ASZ  = 128 * ROWB;
    constexpr int BSZ  = NT * ROWB;
    constexpr int STG  = NP * (ASZ + BSZ);
    constexpr uint32_t SWM = (ROWB == 128) ? 0x70u : 0x30u;

    extern __shared__ char smem[];
    const uint32_t sb = smem_u32(smem);
    const int tid = threadIdx.x, lane = tid & 31, wid = tid >> 5;
    const int nw = wid & 7, mw = wid >> 3;
    const int g = lane >> 2, tq = lane & 3;
    const int m0 = blockIdx.x * 128;
    const int n0 = blockIdx.y * NT;
    const int NC = K / KCH;

    // EPI==2 smem plan: sD [128][258] at 0 (132096B, overlaps staging 98304B after mainloop),
    // cbnS at 132096, sB at 133120, sW at 133696
    float* cbnS = (float*)(smem + 132096);
    if (EPI == 2) for (int i = tid; i < KC_; i += 512) cbnS[i] = g_cbnorm[q*KC_ + i];

    auto sw = [](uint32_t o) { return o ^ ((o >> 3) & SWM); };

    auto load_chunk = [&](int ch, int s) {
        #pragma unroll
        for (int c = 0; c < NP; c++) {
            const __nv_bfloat16* Ap = Apl<EPI>(c);
            uint32_t base = sb + (uint32_t)s*STG + (uint32_t)c*ASZ;
            for (int t = tid; t < ASZ/16; t += 512) {
                int row = t / (ROWB/16), c16 = t % (ROWB/16);
                cp16(base + sw((uint32_t)(row*ROWB + c16*16)),
                     Ap + (size_t)(m0 + row)*K + ch*KCH + c16*8);
            }
            const __nv_bfloat16* Bp = Bpl<EPI>(c, q);
            base = sb + (uint32_t)s*STG + (uint32_t)NP*ASZ + (uint32_t)c*BSZ;
            for (int t = tid; t < BSZ/16; t += 512) {
                int row = t / (ROWB/16), c16 = t % (ROWB/16);
                cp16(base + sw((uint32_t)(row*ROWB + c16*16)),
                     Bp + (size_t)(n0 + row)*K + ch*KCH + c16*8);
            }
        }
        CP_COMMIT();
    };

    load_chunk(0, 0);
    load_chunk(1, 1);

    float acc[4][NF][4];
    #pragma unroll
    for (int i = 0; i < 4; i++)
        #pragma unroll
        for (int j = 0; j < NF; j++)
            #pragma unroll
            for (int r = 0; r < 4; r++) acc[i][j][r] = 0.f;

    const int arow = mw*64 + (lane & 7) + ((lane >> 3) & 1) * 8;
    const int ahalf = (lane >> 4) & 1;
    const int t16 = lane & 15;
    const int brow = nw*WN + (t16 & 7);
    const int bhalf = (t16 >> 3) & 1;

    for (int ch = 0; ch < NC; ch++) {
        if (ch + 1 < NC) cp_wait1(); else cp_wait0();
        __syncthreads();
        const int s = ch & 1;
        const uint32_t Ab = sb + (uint32_t)s*STG;
        const uint32_t Bb = Ab + (uint32_t)NP*ASZ;

        #pragma unroll
        for (int ks = 0; ks < KCH/16; ks++) {
            uint32_t Ar[2][4][4];
            #pragma unroll
            for (int ia = 0; ia < 2; ia++)
                #pragma unroll
                for (int mf = 0; mf < 4; mf++)
                    ldm_x4(Ar[ia][mf],
                           Ab + (uint32_t)ia*ASZ + sw((uint32_t)((arow + mf*16)*ROWB + ks*32 + ahalf*16)));
            #pragma unroll
            for (int ib = 0; ib < NP; ib++) {
                uint32_t Br[NF][2];
                #pragma unroll
                for (int nfi = 0; nfi < NF; nfi++)
                    ldm_x2(Br[nfi],
                           Bb + (uint32_t)ib*BSZ + sw((uint32_t)((brow + nfi*8)*ROWB + ks*32 + bhalf*16)));
                #pragma unroll
                for (int ia = 0; ia < NP; ia++) {
                    if (ia + ib > SUM) break;
                    #pragma unroll
                    for (int mf = 0; mf < 4; mf++)
                        #pragma unroll
                        for (int nfi = 0; nfi < NF; nfi++)
                            mma16816(acc[mf][nfi], Ar[ia][mf], Br[nfi]);
                }
            }
        }
        __syncthreads();
        if (ch + 2 < NC) load_chunk(ch + 2, s);
    }

    // ================= epilogues =================
    if (EPI == 2) {
        float* sD = (float*)smem;             // [128][258]
        int*   sB = (int*)(smem + 133120);    // [128]
        float* sW = (float*)(smem + 133696);  // [16]

        // phase 1: all 256 approx distances per row -> smem
        #pragma unroll
        for (int mf = 0; mf < 4; mf++)
            #pragma unroll
            for (int h = 0; h < 2; h++) {
                int rowl = mw*64 + mf*16 + g + 8*h;
                #pragma unroll
                for (int nfi = 0; nfi < NF; nfi++) {
                    int c0 = nw*WN + nfi*8 + 2*tq;
                    sD[rowl*258 + c0]     = cbnS[c0]     - 2.f*acc[mf][nfi][h*2+0];
                    sD[rowl*258 + c0 + 1] = cbnS[c0 + 1] - 2.f*acc[mf][nfi][h*2+1];
                }
            }
        __syncthreads();

        // phase 2: per-row candidate-exact fp32 argmin (warp per 8 rows)
        for (int r8 = 0; r8 < 8; r8++) {
            int rowl = wid*8 + r8;
            float* drow = sD + rowl*258;
            float bv = FLT_MAX;
            #pragma unroll
            for (int k0 = 0; k0 < KC_; k0 += 32) bv = fminf(bv, drow[k0 + lane]);
            #pragma unroll
            for (int o = 16; o; o >>= 1) bv = fminf(bv, __shfl_xor_sync(0xffffffffu, bv, o));
            const float thr = bv + EPS_CAND;
            const float* rrow = gR + (size_t)(m0 + rowl)*H_;
            float ebv = FLT_MAX; int ebi = KC_;
            #pragma unroll
            for (int k0 = 0; k0 < KC_; k0 += 32) {
                unsigned mask = __ballot_sync(0xffffffffu, drow[k0 + lane] <= thr);
                while (mask) {
                    int j = __ffs(mask) - 1; mask &= mask - 1;
                    int k = k0 + j;
                    const float* cv = cbf + ((size_t)q*KC_ + k)*H_;
                    float s = 0.f;
                    #pragma unroll 4
                    for (int t = lane; t < H_; t += 32) s = fmaf(rrow[t], cv[t], s);
                    #pragma unroll
                    for (int o = 16; o; o >>= 1) s += __shfl_down_sync(0xffffffffu, s, o);
                    s = __shfl_sync(0xffffffffu, s, 0);
                    float de = cbnS[k] - 2.f*s;
                    if (de < ebv) { ebv = de; ebi = k; }   // ascending k + strict '<' = earliest min
                }
            }
            if (lane == 0) sB[rowl] = ebi;
        }
        __syncthreads();

        if (wq && tid < 128)
            idx_out[(size_t)(m0 + tid) * Q_ + q] = (float)sB[tid];

        // residual update: warp w handles rows w*8..w*8+7
        float csw = 0.f;
        for (int r8 = 0; r8 < 8; r8++) {
            int rowl = wid*8 + r8;
            int bi = sB[rowl];
            size_t gr = (size_t)(m0 + rowl);
            const float2* cb2 = (const float2*)(cbf + ((size_t)q*KC_ + bi)*H_);
            float2* R2 = (float2*)(gR + gr*H_);
            float cs = 0.f;
            for (int i = lane; i < H_/2; i += 32) {
                float2 r = R2[i], c = cb2[i];
                float2 rn = { r.x - c.x, r.y - c.y };
                cs += rn.x*rn.x + rn.y*rn.y;
                if (!last) {
                    R2[i] = rn;
                    float h0, m0f, h1, m1f;
                    split2s(rn.x, h0, m0f); split2s(rn.y, h1, m1f);
                    *(uint32_t*)&gRc[0][gr*H_ + 2*i] = bfpack(h0, h1);
                    *(uint32_t*)&gRc[1][gr*H_ + 2*i] = bfpack(m0f, m1f);
                } else {
                    float2 z = ((const float2*)(gZ + gr*H_))[i];
                    float q0 = z.x - rn.x, q1 = z.y - rn.y;
                    float h0, m0f, h1, m1f;
                    split2s(q0, h0, m0f); split2s(q1, h1, m1f);
                    *(uint32_t*)&gQc[0][gr*H_ + 2*i] = bfpack(h0, h1);
                    *(uint32_t*)&gQc[1][gr*H_ + 2*i] = bfpack(m0f, m1f);
                }
            }
            #pragma unroll
            for (int o = 16; o; o >>= 1) cs += __shfl_down_sync(0xffffffffu, cs, o);
            if (lane == 0) csw += cs;
        }
        if (lane == 0) sW[wid] = csw;
        __syncthreads();
        if (tid == 0) {
            float t = 0.f;
            #pragma unroll
            for (int i = 0; i < 16; i++) t += sW[i];
            g_commit[q*512 + blockIdx.x] = t;
        }
    } else {
        const int NOUT = (EPI == 4) ? E_ : H_;
        float lsum = 0.f;
        #pragma unroll
        for (int mf = 0; mf < 4; mf++)
            #pragma unroll
            for (int h = 0; h < 2; h++) {
                int row = m0 + mw*64 + mf*16 + g + 8*h;
                #pragma unroll
                for (int nfi = 0; nfi < NF; nfi++) {
                    int col = n0 + nw*WN + nfi*8 + 2*tq;
                    float v0 = acc[mf][nfi][h*2+0] + __ldg(bias + col);
                    float v1 = acc[mf][nfi][h*2+1] + __ldg(bias + col + 1);
                    if (EPI == 3) { v0 = fmaxf(v0, 0.f); v1 = fmaxf(v1, 0.f); }
                    size_t go = (size_t)row*NOUT + col;
                    if (EPI == 4) {
                        out[go] = v0; out[go+1] = v1;
                        float d0 = v0 - __ldg(xref + go);
                        float d1 = v1 - __ldg(xref + go + 1);
                        lsum = fmaf(d0, d0, fmaf(d1, d1, lsum));
                    } else {
                        float h0, mm0, h1, mm1;
                        split2s(v0, h0, mm0); split2s(v1, h1, mm1);
                        *(uint32_t*)&gGc[0][go] = bfpack(h0, h1);
                        *(uint32_t*)&gGc[1][go] = bfpack(mm0, mm1);
                    }
                }
            }
        if (EPI == 4) {
            float* sW = (float*)smem;
            #pragma unroll
            for (int o = 16; o; o >>= 1) lsum += __shfl_down_sync(0xffffffffu, lsum, o);
            if (lane == 0) sW[wid] = lsum;
            __syncthreads();
            if (tid == 0) {
                float t = 0.f;
                #pragma unroll
                for (int i = 0; i < 16; i++) t += sW[i];
                g_recon[blockIdx.y*512 + blockIdx.x] = t;
            }
        }
    }
}

// ---------------- final scalar reduction ----------------
__global__ void finalize_kernel(float* __restrict__ out) {
    __shared__ double sc[256], sr[256];
    double c = 0.0, r = 0.0;
    for (int i = threadIdx.x; i < Q_*512; i += 256) c += (double)g_commit[i];
    for (int i = threadIdx.x; i < 3*512; i += 256) r += (double)g_recon[i];
    sc[threadIdx.x] = c; sr[threadIdx.x] = r;
    __syncthreads();
    for (int s = 128; s; s >>= 1) {
        if (threadIdx.x < s) { sc[threadIdx.x] += sc[threadIdx.x+s]; sr[threadIdx.x] += sr[threadIdx.x+s]; }
        __syncthreads();
    }
    if (threadIdx.x == 0) {
        out[(size_t)B_*E_ + (size_t)B_*Q_ + 0] = (float)(sr[0] / ((double)B_ * (double)E_));
        out[(size_t)B_*E_ + (size_t)B_*Q_ + 1] = (float)(0.25 * sc[0] / ((double)B_ * (double)H_));
    }
}

// ---------------- launch ----------------
extern "C" void kernel_launch(void* const* d_in, const int* in_sizes, int n_in,
                              void* d_out, int out_size) {
    const float* x   = (const float*)d_in[0];
    const float* We1 = (const float*)d_in[1];
    const float* be1 = (const float*)d_in[2];
    const float* We2 = (const float*)d_in[3];
    const float* be2 = (const float*)d_in[4];
    const float* Wd1 = (const float*)d_in[5];
    const float* bd1 = (const float*)d_in[6];
    const float* Wd2 = (const float*)d_in[7];
    const float* bd2 = (const float*)d_in[8];
    const float* cb  = (const float*)d_in[9];
    float* out = (float*)d_out;

    const int full = out_size >= (int)((size_t)B_*E_ + (size_t)B_*Q_ + 2);
    float* idxo = out + (size_t)B_*E_;

    const int S_DEC = 2*2*(128*128 + 128*128);   // 131072 (NT=128, KCH=64, NP=2)
    const int S_SC  = 134144;                    // sD(132096)+cbn+sB+sW; staging 98304 overlaps sD

    cudaFuncSetAttribute(tc<2,256,32>, cudaFuncAttributeMaxDynamicSharedMemorySize, S_SC);
    cudaFuncSetAttribute(tc<3,128,64>, cudaFuncAttributeMaxDynamicSharedMemorySize, S_DEC);
    cudaFuncSetAttribute(tc<4,128,64>, cudaFuncAttributeMaxDynamicSharedMemorySize, S_DEC);

    prep_weights<<<1024, 256>>>(Wd1, Wd2, cb);
    cbnorm_kernel<<<(Q_*KC_)/8, 256>>>(cb);

    // encoder: fp32 SIMT (proven-accurate z)
    genc<true, 0><<<dim3(H_/128, B_/128), 256>>>(x, We1, be1, B_, H_, E_);
    genc<false,1><<<dim3(H_/128, B_/128), 256>>>(nullptr, We2, be2, B_, H_, H_);

    // residual VQ: tensor scores + candidate-exact fp32 argmin + fused residual update
    for (int q = 0; q < Q_; q++)
        tc<2,256,32><<<dim3(512,1), 512, S_SC>>>(H_, nullptr, q, cb, idxo, full, q == Q_-1, nullptr, nullptr);

    // decoder: tensor 3-term
    tc<3,128,64><<<dim3(512,4), 512, S_DEC>>>(H_, bd1, 0, nullptr, nullptr, 0, 0, nullptr, nullptr);
    tc<4,128,64><<<dim3(512,3), 512, S_DEC>>>(H_, bd2, 0, nullptr, nullptr, 0, 0, out, x);
    if (full) finalize_kernel<<<1, 256>>>(out);
}

// round 14
// speedup vs baseline: 1.4411x; 1.0152x over previous
#include <cuda_runtime.h>
#include <cuda_bf16.h>
#include <cstdint>
#include <cstddef>
#include <cfloat>

#define B_  65536
#define E_  384
#define H_  512
#define KC_ 256
#define Q_  4
#define EPS_CAND 0.25f

// ---------------- static device buffers ----------------
__device__ float g_scratch[(size_t)B_*H_];               // enc hidden (fp32)
__device__ float gZ[(size_t)B_*H_];                      // z (fp32 master)
__device__ float gR[(size_t)B_*H_];                      // residual (fp32 master)
__device__ __nv_bfloat16 gRc[2][(size_t)B_*H_];          // residual split planes (h,m)
__device__ __nv_bfloat16 gQc[2][(size_t)B_*H_];          // quantized split planes
__device__ __nv_bfloat16 gGc[2][(size_t)B_*H_];          // dec hidden split planes
__device__ __nv_bfloat16 gW3c[2][H_*H_];                 // Wd1^T planes [n][k]
__device__ __nv_bfloat16 gW4c[2][E_*H_];                 // Wd2^T planes [n][k]
__device__ __nv_bfloat16 gCBc[2][Q_*KC_*H_];             // codebook planes [code][k]
__device__ float g_cbnorm[Q_*KC_];
__device__ float g_commit[Q_*512];
__device__ float g_recon[3*512];

// ---------------- helpers ----------------
__device__ __forceinline__ uint32_t smem_u32(const void* p) {
    uint32_t a;
    asm("{ .reg .u64 t; cvta.to.shared.u64 t, %1; cvt.u32.u64 %0, t; }" : "=r"(a) : "l"(p));
    return a;
}
__device__ __forceinline__ void cp16(uint32_t s, const void* g) {
    asm volatile("{ .reg .u64 p; cvta.to.global.u64 p, %1; cp.async.cg.shared.global [%0], [p], 16; }"
                 :: "r"(s), "l"(g) : "memory");
}
#define CP_COMMIT() asm volatile("cp.async.commit_group;" ::: "memory")
__device__ __forceinline__ void cp_wait1() { asm volatile("cp.async.wait_group 1;" ::: "memory"); }
__device__ __forceinline__ void cp_wait0() { asm volatile("cp.async.wait_group 0;" ::: "memory"); }

__device__ __forceinline__ void ldm_x4(uint32_t* r, uint32_t a) {
    asm volatile("ldmatrix.sync.aligned.m8n8.x4.shared.b16 {%0,%1,%2,%3}, [%4];"
        : "=r"(r[0]), "=r"(r[1]), "=r"(r[2]), "=r"(r[3]) : "r"(a));
}
__device__ __forceinline__ void ldm_x2(uint32_t* r, uint32_t a) {
    asm volatile("ldmatrix.sync.aligned.m8n8.x2.shared.b16 {%0,%1}, [%2];"
        : "=r"(r[0]), "=r"(r[1]) : "r"(a));
}
__device__ __forceinline__ void mma16816(float* c, const uint32_t* a, const uint32_t* b) {
    asm volatile("mma.sync.aligned.m16n8k16.row.col.f32.bf16.bf16.f32 "
        "{%0,%1,%2,%3}, {%4,%5,%6,%7}, {%8,%9}, {%0,%1,%2,%3};"
        : "+f"(c[0]), "+f"(c[1]), "+f"(c[2]), "+f"(c[3])
        : "r"(a[0]), "r"(a[1]), "r"(a[2]), "r"(a[3]), "r"(b[0]), "r"(b[1]));
}
__device__ __forceinline__ void split2s(float a, float& h, float& m) {
    h = __bfloat162float(__float2bfloat16_rn(a));
    m = a - h;
}
__device__ __forceinline__ uint32_t bfpack(float lo, float hi) {
    __nv_bfloat162 p = __floats2bfloat162_rn(lo, hi);
    return *(uint32_t*)&p;
}

// ---------------- prep kernels ----------------
__global__ void prep_weights(const float* __restrict__ W3, const float* __restrict__ W4,
                             const float* __restrict__ cb) {
    size_t stride = (size_t)gridDim.x * blockDim.x;
    size_t i0 = (size_t)blockIdx.x*blockDim.x + threadIdx.x;
    for (size_t t = i0; t < (size_t)H_*H_; t += stride) {
        size_t n = t / H_, k = t % H_;
        float h, m; split2s(W3[k*H_ + n], h, m);
        gW3c[0][t] = __float2bfloat16_rn(h); gW3c[1][t] = __float2bfloat16_rn(m);
    }
    for (size_t t = i0; t < (size_t)E_*H_; t += stride) {
        size_t n = t / H_, k = t % H_;
        float h, m; split2s(W4[k*E_ + n], h, m);
        gW4c[0][t] = __float2bfloat16_rn(h); gW4c[1][t] = __float2bfloat16_rn(m);
    }
    for (size_t t = i0; t < (size_t)Q_*KC_*H_; t += stride) {
        float h, m; split2s(cb[t], h, m);
        gCBc[0][t] = __float2bfloat16_rn(h); gCBc[1][t] = __float2bfloat16_rn(m);
    }
}
__global__ void cbnorm_kernel(const float* __restrict__ cb) {
    int warp = (blockIdx.x*blockDim.x + threadIdx.x) >> 5;
    int lane = threadIdx.x & 31;
    if (warp >= Q_*KC_) return;
    const float* v = cb + (size_t)warp * H_;
    float s = 0.f;
    for (int i = lane; i < H_; i += 32) s = fmaf(v[i], v[i], s);
    #pragma unroll
    for (int o = 16; o; o >>= 1) s += __shfl_down_sync(0xffffffffu, s, o);
    if (lane == 0) g_cbnorm[warp] = s;
}

// ---------------- SIMT fp32 encoder GEMM: double-buffered, vector-LDS ----------------
// Same per-thread FFMA order as the proven R3/R12 kernel -> z is bit-identical.
// MODE 0: enc1  C = relu(x @ W1 + b1) -> g_scratch
// MODE 1: enc2  z = scratch @ W2 + b2 -> gZ, gR (fp32) + gRc split planes
template<bool RELU, int MODE>
__global__ __launch_bounds__(256) void genc(
    const float* __restrict__ Aext, const float* __restrict__ W,
    const float* __restrict__ bias, int M, int N, int K)
{
    __shared__ __align__(16) float As[2][8][132];
    __shared__ __align__(16) float Ws[2][8][132];

    const float* A = (MODE == 0) ? Aext : g_scratch;

    const int tid = threadIdx.x;
    const int m0 = blockIdx.y * 128;
    const int n0 = blockIdx.x * 128;

    const int ar = tid >> 1;          // A tile row 0..127
    const int ac = (tid & 1) * 4;     // A tile k offset 0/4
    const int wr = tid >> 5;          // W: k 0..7
    const int wc = (tid & 31) * 4;    // W: n offset
    const int tx = tid & 15;
    const int ty = tid >> 4;

    float acc[8][8];
    #pragma unroll
    for (int i = 0; i < 8; i++)
        #pragma unroll
        for (int j = 0; j < 8; j++) acc[i][j] = 0.f;

    // prologue: stage 0
    {
        float4 av = *(const float4*)(A + (size_t)(m0 + ar) * K + ac);
        As[0][ac + 0][ar] = av.x; As[0][ac + 1][ar] = av.y;
        As[0][ac + 2][ar] = av.z; As[0][ac + 3][ar] = av.w;
        float4 wv = *(const float4*)(W + (size_t)wr * N + n0 + wc);
        *(float4*)&Ws[0][wr][wc] = wv;
    }
    __syncthreads();

    for (int k0 = 0; k0 < K; k0 += 8) {
        const int s = (k0 >> 3) & 1;
        const bool more = (k0 + 8 < K);
        float4 av, wv;
        if (more) {
            av = *(const float4*)(A + (size_t)(m0 + ar) * K + (k0 + 8) + ac);
            wv = *(const float4*)(W + (size_t)(k0 + 8 + wr) * N + n0 + wc);
        }

        #pragma unroll
        for (int kk = 0; kk < 8; kk++) {
            float4 a0 = *(const float4*)&As[s][kk][ty * 8];
            float4 a1 = *(const float4*)&As[s][kk][ty * 8 + 4];
            float4 b0 = *(const float4*)&Ws[s][kk][tx * 8];
            float4 b1 = *(const float4*)&Ws[s][kk][tx * 8 + 4];
            float areg[8] = { a0.x, a0.y, a0.z, a0.w, a1.x, a1.y, a1.z, a1.w };
            float breg[8] = { b0.x, b0.y, b0.z, b0.w, b1.x, b1.y, b1.z, b1.w };
            #pragma unroll
            for (int i = 0; i < 8; i++)
                #pragma unroll
                for (int j = 0; j < 8; j++)
                    acc[i][j] = fmaf(areg[i], breg[j], acc[i][j]);
        }

        if (more) {
            As[s ^ 1][ac + 0][ar] = av.x; As[s ^ 1][ac + 1][ar] = av.y;
            As[s ^ 1][ac + 2][ar] = av.z; As[s ^ 1][ac + 3][ar] = av.w;
            *(float4*)&Ws[s ^ 1][wr][wc] = wv;
        }
        __syncthreads();
    }

    #pragma unroll
    for (int i = 0; i < 8; i++) {
        const int row = m0 + ty * 8 + i;
        #pragma unroll
        for (int j = 0; j < 8; j++) {
            const int col = n0 + tx * 8 + j;
            float v = acc[i][j] + __ldg(bias + col);
            if (RELU) v = fmaxf(v, 0.f);
            size_t go = (size_t)row * N + col;
            if (MODE == 0) {
                g_scratch[go] = v;
            } else {
                gZ[go] = v; gR[go] = v;
                float h, m; split2s(v, h, m);
                gRc[0][go] = __float2bfloat16_rn(h);
                gRc[1][go] = __float2bfloat16_rn(m);
            }
        }
    }
}

// ---------------- plane selectors (tensor path) ----------------
template<int EPI> __device__ __forceinline__ const __nv_bfloat16* Apl(int c) {
    if (EPI == 2) return gRc[c];
    if (EPI == 3) return gQc[c];
    return gGc[c];
}
template<int EPI> __device__ __forceinline__ const __nv_bfloat16* Bpl(int c, int q) {
    if (EPI == 2) return gCBc[c] + (size_t)q*KC_*H_;
    if (EPI == 3) return gW3c[c];
    return gW4c[c];
}

// ---------------- tensor-core GEMM (3-term split) with fused epilogues ----------------
// EPI: 2=scores(candidate-exact argmin + residual update) 3=dec1(relu->gGc) 4=dec2(out+loss)
template<int EPI, int NT, int KCH>
__global__ __launch_bounds__(512, 1) void tc(
    int K, const float* __restrict__ bias,
    int q, const float* __restrict__ cbf, float* __restrict__ idx_out, int wq, int last,
    float* __restrict__ out, const float* __restrict__ xref)
{
    constexpr int NP   = 2;
    constexpr int SUM  = 1;
    constexpr int ROWB = KCH * 2;
    constexpr int WN   = NT / 8;
    constexpr int NF   = WN / 8;
    constexpr int ASZ  = 128 * ROWB;
    constexpr int BSZ  = NT * ROWB;
    constexpr int STG  = NP * (ASZ + BSZ);
    constexpr uint32_t SWM = (ROWB == 128) ? 0x70u : 0x30u;

    extern __shared__ char smem[];
    const uint32_t sb = smem_u32(smem);
    const int tid = threadIdx.x, lane = tid & 31, wid = tid >> 5;
    const int nw = wid & 7, mw = wid >> 3;
    const int g = lane >> 2, tq = lane & 3;
    const int m0 = blockIdx.x * 128;
    const int n0 = blockIdx.y * NT;
    const int NC = K / KCH;

    // EPI==2 smem plan: sD [128][258] at 0 (132096B, overlaps staging after mainloop),
    // cbnS at 132096, sB at 133120, sW at 133696
    float* cbnS = (float*)(smem + 132096);
    if (EPI == 2) for (int i = tid; i < KC_; i += 512) cbnS[i] = g_cbnorm[q*KC_ + i];

    auto sw = [](uint32_t o) { return o ^ ((o >> 3) & SWM); };

    auto load_chunk = [&](int ch, int s) {
        #pragma unroll
        for (int c = 0; c < NP; c++) {
            const __nv_bfloat16* Ap = Apl<EPI>(c);
            uint32_t base = sb + (uint32_t)s*STG + (uint32_t)c*ASZ;
            for (int t = tid; t < ASZ/16; t += 512) {
                int row = t / (ROWB/16), c16 = t % (ROWB/16);
                cp16(base + sw((uint32_t)(row*ROWB + c16*16)),
                     Ap + (size_t)(m0 + row)*K + ch*KCH + c16*8);
            }
            const __nv_bfloat16* Bp = Bpl<EPI>(c, q);
            base = sb + (uint32_t)s*STG + (uint32_t)NP*ASZ + (uint32_t)c*BSZ;
            for (int t = tid; t < BSZ/16; t += 512) {
                int row = t / (ROWB/16), c16 = t % (ROWB/16);
                cp16(base + sw((uint32_t)(row*ROWB + c16*16)),
                     Bp + (size_t)(n0 + row)*K + ch*KCH + c16*8);
            }
        }
        CP_COMMIT();
    };

    load_chunk(0, 0);
    load_chunk(1, 1);

    float acc[4][NF][4];
    #pragma unroll
    for (int i = 0; i < 4; i++)
        #pragma unroll
        for (int j = 0; j < NF; j++)
            #pragma unroll
            for (int r = 0; r < 4; r++) acc[i][j][r] = 0.f;

    const int arow = mw*64 + (lane & 7) + ((lane >> 3) & 1) * 8;
    const int ahalf = (lane >> 4) & 1;
    const int t16 = lane & 15;
    const int brow = nw*WN + (t16 & 7);
    const int bhalf = (t16 >> 3) & 1;

    for (int ch = 0; ch < NC; ch++) {
        if (ch + 1 < NC) cp_wait1(); else cp_wait0();
        __syncthreads();
        const int s = ch & 1;
        const uint32_t Ab = sb + (uint32_t)s*STG;
        const uint32_t Bb = Ab + (uint32_t)NP*ASZ;

        #pragma unroll
        for (int ks = 0; ks < KCH/16; ks++) {
            uint32_t Ar[2][4][4];
            #pragma unroll
            for (int ia = 0; ia < 2; ia++)
                #pragma unroll
                for (int mf = 0; mf < 4; mf++)
                    ldm_x4(Ar[ia][mf],
                           Ab + (uint32_t)ia*ASZ + sw((uint32_t)((arow + mf*16)*ROWB + ks*32 + ahalf*16)));
            #pragma unroll
            for (int ib = 0; ib < NP; ib++) {
                uint32_t Br[NF][2];
                #pragma unroll
                for (int nfi = 0; nfi < NF; nfi++)
                    ldm_x2(Br[nfi],
                           Bb + (uint32_t)ib*BSZ + sw((uint32_t)((brow + nfi*8)*ROWB + ks*32 + bhalf*16)));
                #pragma unroll
                for (int ia = 0; ia < NP; ia++) {
                    if (ia + ib > SUM) break;
                    #pragma unroll
                    for (int mf = 0; mf < 4; mf++)
                        #pragma unroll
                        for (int nfi = 0; nfi < NF; nfi++)
                            mma16816(acc[mf][nfi], Ar[ia][mf], Br[nfi]);
                }
            }
        }
        __syncthreads();
        if (ch + 2 < NC) load_chunk(ch + 2, s);
    }

    // ================= epilogues =================
    if (EPI == 2) {
        float* sD = (float*)smem;             // [128][258]
        int*   sB = (int*)(smem + 133120);    // [128]
        float* sW = (float*)(smem + 133696);  // [16]

        // phase 1: all 256 approx distances per row -> smem
        #pragma unroll
        for (int mf = 0; mf < 4; mf++)
            #pragma unroll
            for (int h = 0; h < 2; h++) {
                int rowl = mw*64 + mf*16 + g + 8*h;
                #pragma unroll
                for (int nfi = 0; nfi < NF; nfi++) {
                    int c0 = nw*WN + nfi*8 + 2*tq;
                    sD[rowl*258 + c0]     = cbnS[c0]     - 2.f*acc[mf][nfi][h*2+0];
                    sD[rowl*258 + c0 + 1] = cbnS[c0 + 1] - 2.f*acc[mf][nfi][h*2+1];
                }
            }
        __syncthreads();

        // phase 2: per-row candidate-exact fp32 argmin (warp per 8 rows)
        for (int r8 = 0; r8 < 8; r8++) {
            int rowl = wid*8 + r8;
            float* drow = sD + rowl*258;
            float bv = FLT_MAX;
            #pragma unroll
            for (int k0 = 0; k0 < KC_; k0 += 32) bv = fminf(bv, drow[k0 + lane]);
            #pragma unroll
            for (int o = 16; o; o >>= 1) bv = fminf(bv, __shfl_xor_sync(0xffffffffu, bv, o));
            const float thr = bv + EPS_CAND;
            const float* rrow = gR + (size_t)(m0 + rowl)*H_;
            float ebv = FLT_MAX; int ebi = KC_;
            #pragma unroll
            for (int k0 = 0; k0 < KC_; k0 += 32) {
                unsigned mask = __ballot_sync(0xffffffffu, drow[k0 + lane] <= thr);
                while (mask) {
                    int j = __ffs(mask) - 1; mask &= mask - 1;
                    int k = k0 + j;
                    const float* cv = cbf + ((size_t)q*KC_ + k)*H_;
                    float s = 0.f;
                    #pragma unroll 4
                    for (int t = lane; t < H_; t += 32) s = fmaf(rrow[t], cv[t], s);
                    #pragma unroll
                    for (int o = 16; o; o >>= 1) s += __shfl_down_sync(0xffffffffu, s, o);
                    s = __shfl_sync(0xffffffffu, s, 0);
                    float de = cbnS[k] - 2.f*s;
                    if (de < ebv) { ebv = de; ebi = k; }   // ascending k + strict '<' = earliest min
                }
            }
            if (lane == 0) sB[rowl] = ebi;
        }
        __syncthreads();

        if (wq && tid < 128)
            idx_out[(size_t)(m0 + tid) * Q_ + q] = (float)sB[tid];

        // residual update: warp w handles rows w*8..w*8+7
        float csw = 0.f;
        for (int r8 = 0; r8 < 8; r8++) {
            int rowl = wid*8 + r8;
            int bi = sB[rowl];
            size_t gr = (size_t)(m0 + rowl);
            const float2* cb2 = (const float2*)(cbf + ((size_t)q*KC_ + bi)*H_);
            float2* R2 = (float2*)(gR + gr*H_);
            float cs = 0.f;
            for (int i = lane; i < H_/2; i += 32) {
                float2 r = R2[i], c = cb2[i];
                float2 rn = { r.x - c.x, r.y - c.y };
                cs += rn.x*rn.x + rn.y*rn.y;
                if (!last) {
                    R2[i] = rn;
                    float h0, m0f, h1, m1f;
                    split2s(rn.x, h0, m0f); split2s(rn.y, h1, m1f);
                    *(uint32_t*)&gRc[0][gr*H_ + 2*i] = bfpack(h0, h1);
                    *(uint32_t*)&gRc[1][gr*H_ + 2*i] = bfpack(m0f, m1f);
                } else {
                    float2 z = ((const float2*)(gZ + gr*H_))[i];
                    float q0 = z.x - rn.x, q1 = z.y - rn.y;
                    float h0, m0f, h1, m1f;
                    split2s(q0, h0, m0f); split2s(q1, h1, m1f);
                    *(uint32_t*)&gQc[0][gr*H_ + 2*i] = bfpack(h0, h1);
                    *(uint32_t*)&gQc[1][gr*H_ + 2*i] = bfpack(m0f, m1f);
                }
            }
            #pragma unroll
            for (int o = 16; o; o >>= 1) cs += __shfl_down_sync(0xffffffffu, cs, o);
            if (lane == 0) csw += cs;
        }
        if (lane == 0) sW[wid] = csw;
        __syncthreads();
        if (tid == 0) {
            float t = 0.f;
            #pragma unroll
            for (int i = 0; i < 16; i++) t += sW[i];
            g_commit[q*512 + blockIdx.x] = t;
        }
    } else {
        const int NOUT = (EPI == 4) ? E_ : H_;
        float lsum = 0.f;
        #pragma unroll
        for (int mf = 0; mf < 4; mf++)
            #pragma unroll
            for (int h = 0; h < 2; h++) {
                int row = m0 + mw*64 + mf*16 + g + 8*h;
                #pragma unroll
                for (int nfi = 0; nfi < NF; nfi++) {
                    int col = n0 + nw*WN + nfi*8 + 2*tq;
                    float v0 = acc[mf][nfi][h*2+0] + __ldg(bias + col);
                    float v1 = acc[mf][nfi][h*2+1] + __ldg(bias + col + 1);
                    if (EPI == 3) { v0 = fmaxf(v0, 0.f); v1 = fmaxf(v1, 0.f); }
                    size_t go = (size_t)row*NOUT + col;
                    if (EPI == 4) {
                        out[go] = v0; out[go+1] = v1;
                        float d0 = v0 - __ldg(xref + go);
                        float d1 = v1 - __ldg(xref + go + 1);
                        lsum = fmaf(d0, d0, fmaf(d1, d1, lsum));
                    } else {
                        float h0, mm0, h1, mm1;
                        split2s(v0, h0, mm0); split2s(v1, h1, mm1);
                        *(uint32_t*)&gGc[0][go] = bfpack(h0, h1);
                        *(uint32_t*)&gGc[1][go] = bfpack(mm0, mm1);
                    }
                }
            }
        if (EPI == 4) {
            float* sW = (float*)smem;
            #pragma unroll
            for (int o = 16; o; o >>= 1) lsum += __shfl_down_sync(0xffffffffu, lsum, o);
            if (lane == 0) sW[wid] = lsum;
            __syncthreads();
            if (tid == 0) {
                float t = 0.f;
                #pragma unroll
                for (int i = 0; i < 16; i++) t += sW[i];
                g_recon[blockIdx.y*512 + blockIdx.x] = t;
            }
        }
    }
}

// ---------------- final scalar reduction ----------------
__global__ void finalize_kernel(float* __restrict__ out) {
    __shared__ double sc[256], sr[256];
    double c = 0.0, r = 0.0;
    for (int i = threadIdx.x; i < Q_*512; i += 256) c += (double)g_commit[i];
    for (int i = threadIdx.x; i < 3*512; i += 256) r += (double)g_recon[i];
    sc[threadIdx.x] = c; sr[threadIdx.x] = r;
    __syncthreads();
    for (int s = 128; s; s >>= 1) {
        if (threadIdx.x < s) { sc[threadIdx.x] += sc[threadIdx.x+s]; sr[threadIdx.x] += sr[threadIdx.x+s]; }
        __syncthreads();
    }
    if (threadIdx.x == 0) {
        out[(size_t)B_*E_ + (size_t)B_*Q_ + 0] = (float)(sr[0] / ((double)B_ * (double)E_));
        out[(size_t)B_*E_ + (size_t)B_*Q_ + 1] = (float)(0.25 * sc[0] / ((double)B_ * (double)H_));
    }
}

// ---------------- launch ----------------
extern "C" void kernel_launch(void* const* d_in, const int* in_sizes, int n_in,
                              void* d_out, int out_size) {
    const float* x   = (const float*)d_in[0];
    const float* We1 = (const float*)d_in[1];
    const float* be1 = (const float*)d_in[2];
    const float* We2 = (const float*)d_in[3];
    const float* be2 = (const float*)d_in[4];
    const float* Wd1 = (const float*)d_in[5];
    const float* bd1 = (const float*)d_in[6];
    const float* Wd2 = (const float*)d_in[7];
    const float* bd2 = (const float*)d_in[8];
    const float* cb  = (const float*)d_in[9];
    float* out = (float*)d_out;

    const int full = out_size >= (int)((size_t)B_*E_ + (size_t)B_*Q_ + 2);
    float* idxo = out + (size_t)B_*E_;

    const int S_DEC = 2*2*(128*128 + 128*128);   // 131072 (NT=128, KCH=64, NP=2)
    const int S_SC  = 134144;                    // sD(132096)+cbn+sB+sW; staging 98304 overlaps sD

    cudaFuncSetAttribute(tc<2,256,32>, cudaFuncAttributeMaxDynamicSharedMemorySize, S_SC);
    cudaFuncSetAttribute(tc<3,128,64>, cudaFuncAttributeMaxDynamicSharedMemorySize, S_DEC);
    cudaFuncSetAttribute(tc<4,128,64>, cudaFuncAttributeMaxDynamicSharedMemorySize, S_DEC);

    prep_weights<<<1024, 256>>>(Wd1, Wd2, cb);
    cbnorm_kernel<<<(Q_*KC_)/8, 256>>>(cb);

    // encoder: fp32 SIMT (proven-accurate z), double-buffered + vector LDS
    genc<true, 0><<<dim3(H_/128, B_/128), 256>>>(x, We1, be1, B_, H_, E_);
    genc<false,1><<<dim3(H_/128, B_/128), 256>>>(nullptr, We2, be2, B_, H_, H_);

    // residual VQ: tensor scores + candidate-exact fp32 argmin + fused residual update
    for (int q = 0; q < Q_; q++)
        tc<2,256,32><<<dim3(512,1), 512, S_SC>>>(H_, nullptr, q, cb, idxo, full, q == Q_-1, nullptr, nullptr);

    // decoder: tensor 3-term
    tc<3,128,64><<<dim3(512,4), 512, S_DEC>>>(H_, bd1, 0, nullptr, nullptr, 0, 0, nullptr, nullptr);
    tc<4,128,64><<<dim3(512,3), 512, S_DEC>>>(H_, bd2, 0, nullptr, nullptr, 0, 0, out, x);
    if (full) finalize_kernel<<<1, 256>>>(out);
}

// round 15
// speedup vs baseline: 1.6367x; 1.1358x over previous
#include <cuda_runtime.h>
#include <cuda_bf16.h>
#include <cstdint>
#include <cstddef>
#include <cfloat>

#define B_  65536
#define E_  384
#define H_  512
#define KC_ 256
#define Q_  4
#define EPS_CAND 1.0f

// ---------------- static device buffers ----------------
__device__ float g_scratch[(size_t)B_*H_];               // enc hidden (fp32)
__device__ float gZ[(size_t)B_*H_];                      // z (fp32 master)
__device__ float gR[(size_t)B_*H_];                      // residual (fp32 master)
__device__ __nv_bfloat16 gRc[1][(size_t)B_*H_];          // residual h-plane (scores are 1-term)
__device__ __nv_bfloat16 gQc[2][(size_t)B_*H_];          // quantized split planes
__device__ __nv_bfloat16 gGc[2][(size_t)B_*H_];          // dec hidden split planes
__device__ __nv_bfloat16 gW3c[2][H_*H_];                 // Wd1^T planes [n][k]
__device__ __nv_bfloat16 gW4c[2][E_*H_];                 // Wd2^T planes [n][k]
__device__ __nv_bfloat16 gCBc[1][Q_*KC_*H_];             // codebook h-plane [code][k]
__device__ float g_cbnorm[Q_*KC_];
__device__ float g_commit[Q_*512];
__device__ float g_recon[3*512];

// ---------------- helpers ----------------
__device__ __forceinline__ uint32_t smem_u32(const void* p) {
    uint32_t a;
    asm("{ .reg .u64 t; cvta.to.shared.u64 t, %1; cvt.u32.u64 %0, t; }" : "=r"(a) : "l"(p));
    return a;
}
__device__ __forceinline__ void cp16(uint32_t s, const void* g) {
    asm volatile("{ .reg .u64 p; cvta.to.global.u64 p, %1; cp.async.cg.shared.global [%0], [p], 16; }"
                 :: "r"(s), "l"(g) : "memory");
}
#define CP_COMMIT() asm volatile("cp.async.commit_group;" ::: "memory")
__device__ __forceinline__ void cp_wait1() { asm volatile("cp.async.wait_group 1;" ::: "memory"); }
__device__ __forceinline__ void cp_wait0() { asm volatile("cp.async.wait_group 0;" ::: "memory"); }

__device__ __forceinline__ void ldm_x4(uint32_t* r, uint32_t a) {
    asm volatile("ldmatrix.sync.aligned.m8n8.x4.shared.b16 {%0,%1,%2,%3}, [%4];"
        : "=r"(r[0]), "=r"(r[1]), "=r"(r[2]), "=r"(r[3]) : "r"(a));
}
__device__ __forceinline__ void ldm_x2(uint32_t* r, uint32_t a) {
    asm volatile("ldmatrix.sync.aligned.m8n8.x2.shared.b16 {%0,%1}, [%2];"
        : "=r"(r[0]), "=r"(r[1]) : "r"(a));
}
__device__ __forceinline__ void mma16816(float* c, const uint32_t* a, const uint32_t* b) {
    asm volatile("mma.sync.aligned.m16n8k16.row.col.f32.bf16.bf16.f32 "
        "{%0,%1,%2,%3}, {%4,%5,%6,%7}, {%8,%9}, {%0,%1,%2,%3};"
        : "+f"(c[0]), "+f"(c[1]), "+f"(c[2]), "+f"(c[3])
        : "r"(a[0]), "r"(a[1]), "r"(a[2]), "r"(a[3]), "r"(b[0]), "r"(b[1]));
}
__device__ __forceinline__ void split2s(float a, float& h, float& m) {
    h = __bfloat162float(__float2bfloat16_rn(a));
    m = a - h;
}
__device__ __forceinline__ uint32_t bfpack(float lo, float hi) {
    __nv_bfloat162 p = __floats2bfloat162_rn(lo, hi);
    return *(uint32_t*)&p;
}

// ---------------- prep kernels ----------------
__global__ void prep_weights(const float* __restrict__ W3, const float* __restrict__ W4,
                             const float* __restrict__ cb) {
    size_t stride = (size_t)gridDim.x * blockDim.x;
    size_t i0 = (size_t)blockIdx.x*blockDim.x + threadIdx.x;
    for (size_t t = i0; t < (size_t)H_*H_; t += stride) {
        size_t n = t / H_, k = t % H_;
        float h, m; split2s(W3[k*H_ + n], h, m);
        gW3c[0][t] = __float2bfloat16_rn(h); gW3c[1][t] = __float2bfloat16_rn(m);
    }
    for (size_t t = i0; t < (size_t)E_*H_; t += stride) {
        size_t n = t / H_, k = t % H_;
        float h, m; split2s(W4[k*E_ + n], h, m);
        gW4c[0][t] = __float2bfloat16_rn(h); gW4c[1][t] = __float2bfloat16_rn(m);
    }
    for (size_t t = i0; t < (size_t)Q_*KC_*H_; t += stride) {
        gCBc[0][t] = __float2bfloat16_rn(cb[t]);
    }
}
__global__ void cbnorm_kernel(const float* __restrict__ cb) {
    int warp = (blockIdx.x*blockDim.x + threadIdx.x) >> 5;
    int lane = threadIdx.x & 31;
    if (warp >= Q_*KC_) return;
    const float* v = cb + (size_t)warp * H_;
    float s = 0.f;
    for (int i = lane; i < H_; i += 32) s = fmaf(v[i], v[i], s);
    #pragma unroll
    for (int o = 16; o; o >>= 1) s += __shfl_down_sync(0xffffffffu, s, o);
    if (lane == 0) g_cbnorm[warp] = s;
}

// ---------------- SIMT fp32 encoder GEMM: double-buffered, vector-LDS ----------------
// Same per-thread FFMA order as the proven R3/R12 kernel -> z is bit-identical.
template<bool RELU, int MODE>
__global__ __launch_bounds__(256) void genc(
    const float* __restrict__ Aext, const float* __restrict__ W,
    const float* __restrict__ bias, int M, int N, int K)
{
    __shared__ __align__(16) float As[2][8][132];
    __shared__ __align__(16) float Ws[2][8][132];

    const float* A = (MODE == 0) ? Aext : g_scratch;

    const int tid = threadIdx.x;
    const int m0 = blockIdx.y * 128;
    const int n0 = blockIdx.x * 128;

    const int ar = tid >> 1;
    const int ac = (tid & 1) * 4;
    const int wr = tid >> 5;
    const int wc = (tid & 31) * 4;
    const int tx = tid & 15;
    const int ty = tid >> 4;

    float acc[8][8];
    #pragma unroll
    for (int i = 0; i < 8; i++)
        #pragma unroll
        for (int j = 0; j < 8; j++) acc[i][j] = 0.f;

    {
        float4 av = *(const float4*)(A + (size_t)(m0 + ar) * K + ac);
        As[0][ac + 0][ar] = av.x; As[0][ac + 1][ar] = av.y;
        As[0][ac + 2][ar] = av.z; As[0][ac + 3][ar] = av.w;
        float4 wv = *(const float4*)(W + (size_t)wr * N + n0 + wc);
        *(float4*)&Ws[0][wr][wc] = wv;
    }
    __syncthreads();

    for (int k0 = 0; k0 < K; k0 += 8) {
        const int s = (k0 >> 3) & 1;
        const bool more = (k0 + 8 < K);
        float4 av, wv;
        if (more) {
            av = *(const float4*)(A + (size_t)(m0 + ar) * K + (k0 + 8) + ac);
            wv = *(const float4*)(W + (size_t)(k0 + 8 + wr) * N + n0 + wc);
        }

        #pragma unroll
        for (int kk = 0; kk < 8; kk++) {
            float4 a0 = *(const float4*)&As[s][kk][ty * 8];
            float4 a1 = *(const float4*)&As[s][kk][ty * 8 + 4];
            float4 b0 = *(const float4*)&Ws[s][kk][tx * 8];
            float4 b1 = *(const float4*)&Ws[s][kk][tx * 8 + 4];
            float areg[8] = { a0.x, a0.y, a0.z, a0.w, a1.x, a1.y, a1.z, a1.w };
            float breg[8] = { b0.x, b0.y, b0.z, b0.w, b1.x, b1.y, b1.z, b1.w };
            #pragma unroll
            for (int i = 0; i < 8; i++)
                #pragma unroll
                for (int j = 0; j < 8; j++)
                    acc[i][j] = fmaf(areg[i], breg[j], acc[i][j]);
        }

        if (more) {
            As[s ^ 1][ac + 0][ar] = av.x; As[s ^ 1][ac + 1][ar] = av.y;
            As[s ^ 1][ac + 2][ar] = av.z; As[s ^ 1][ac + 3][ar] = av.w;
            *(float4*)&Ws[s ^ 1][wr][wc] = wv;
        }
        __syncthreads();
    }

    #pragma unroll
    for (int i = 0; i < 8; i++) {
        const int row = m0 + ty * 8 + i;
        #pragma unroll
        for (int j = 0; j < 8; j++) {
            const int col = n0 + tx * 8 + j;
            float v = acc[i][j] + __ldg(bias + col);
            if (RELU) v = fmaxf(v, 0.f);
            size_t go = (size_t)row * N + col;
            if (MODE == 0) {
                g_scratch[go] = v;
            } else {
                gZ[go] = v; gR[go] = v;
                gRc[0][go] = __float2bfloat16_rn(v);   // h-plane only (1-term scores)
            }
        }
    }
}

// ---------------- plane selectors (tensor path) ----------------
template<int EPI> __device__ __forceinline__ const __nv_bfloat16* Apl(int c) {
    if (EPI == 2) return gRc[0];
    if (EPI == 3) return gQc[c];
    return gGc[c];
}
template<int EPI> __device__ __forceinline__ const __nv_bfloat16* Bpl(int c, int q) {
    if (EPI == 2) return gCBc[0] + (size_t)q*KC_*H_;
    if (EPI == 3) return gW3c[c];
    return gW4c[c];
}

// ---------------- tensor-core GEMM with fused epilogues ----------------
// EPI: 2=scores(1-term, candidate-exact argmin + residual update) 3=dec1 4=dec2 (3-term)
// SUM: max split-order kept; NP = SUM+1 planes staged.
template<int EPI, int NT, int KCH, int SUM>
__global__ __launch_bounds__(512, 1) void tc(
    int K, const float* __restrict__ bias,
    int q, const float* __restrict__ cbf, float* __restrict__ idx_out, int wq, int last,
    float* __restrict__ out, const float* __restrict__ xref)
{
    constexpr int NP   = SUM + 1;
    constexpr int ROWB = KCH * 2;
    constexpr int WN   = NT / 8;
    constexpr int NF   = WN / 8;
    constexpr int ASZ  = 128 * ROWB;
    constexpr int BSZ  = NT * ROWB;
    constexpr int STG  = NP * (ASZ + BSZ);
    constexpr uint32_t SWM = (ROWB == 128) ? 0x70u : 0x30u;

    extern __shared__ char smem[];
    const uint32_t sb = smem_u32(smem);
    const int tid = threadIdx.x, lane = tid & 31, wid = tid >> 5;
    const int nw = wid & 7, mw = wid >> 3;
    const int g = lane >> 2, tq = lane & 3;
    const int m0 = blockIdx.x * 128;
    const int n0 = blockIdx.y * NT;
    const int NC = K / KCH;

    // EPI==2 smem plan: sD [128][258] at 0 (132096B, overlaps staging after mainloop),
    // cbnS at 132096, sB at 133120, sW at 133696
    float* cbnS = (float*)(smem + 132096);
    if (EPI == 2) for (int i = tid; i < KC_; i += 512) cbnS[i] = g_cbnorm[q*KC_ + i];

    auto sw = [](uint32_t o) { return o ^ ((o >> 3) & SWM); };

    auto load_chunk = [&](int ch, int s) {
        #pragma unroll
        for (int c = 0; c < NP; c++) {
            const __nv_bfloat16* Ap = Apl<EPI>(c);
            uint32_t base = sb + (uint32_t)s*STG + (uint32_t)c*ASZ;
            for (int t = tid; t < ASZ/16; t += 512) {
                int row = t / (ROWB/16), c16 = t % (ROWB/16);
                cp16(base + sw((uint32_t)(row*ROWB + c16*16)),
                     Ap + (size_t)(m0 + row)*K + ch*KCH + c16*8);
            }
            const __nv_bfloat16* Bp = Bpl<EPI>(c, q);
            base = sb + (uint32_t)s*STG + (uint32_t)NP*ASZ + (uint32_t)c*BSZ;
            for (int t = tid; t < BSZ/16; t += 512) {
                int row = t / (ROWB/16), c16 = t % (ROWB/16);
                cp16(base + sw((uint32_t)(row*ROWB + c16*16)),
                     Bp + (size_t)(n0 + row)*K + ch*KCH + c16*8);
            }
        }
        CP_COMMIT();
    };

    load_chunk(0, 0);
    load_chunk(1, 1);

    float acc[4][NF][4];
    #pragma unroll
    for (int i = 0; i < 4; i++)
        #pragma unroll
        for (int j = 0; j < NF; j++)
            #pragma unroll
            for (int r = 0; r < 4; r++) acc[i][j][r] = 0.f;

    const int arow = mw*64 + (lane & 7) + ((lane >> 3) & 1) * 8;
    const int ahalf = (lane >> 4) & 1;
    const int t16 = lane & 15;
    const int brow = nw*WN + (t16 & 7);
    const int bhalf = (t16 >> 3) & 1;

    for (int ch = 0; ch < NC; ch++) {
        if (ch + 1 < NC) cp_wait1(); else cp_wait0();
        __syncthreads();
        const int s = ch & 1;
        const uint32_t Ab = sb + (uint32_t)s*STG;
        const uint32_t Bb = Ab + (uint32_t)NP*ASZ;

        #pragma unroll
        for (int ks = 0; ks < KCH/16; ks++) {
            uint32_t Ar[NP][4][4];
            #pragma unroll
            for (int ia = 0; ia < NP; ia++)
                #pragma unroll
                for (int mf = 0; mf < 4; mf++)
                    ldm_x4(Ar[ia][mf],
                           Ab + (uint32_t)ia*ASZ + sw((uint32_t)((arow + mf*16)*ROWB + ks*32 + ahalf*16)));
            #pragma unroll
            for (int ib = 0; ib < NP; ib++) {
                uint32_t Br[NF][2];
                #pragma unroll
                for (int nfi = 0; nfi < NF; nfi++)
                    ldm_x2(Br[nfi],
                           Bb + (uint32_t)ib*BSZ + sw((uint32_t)((brow + nfi*8)*ROWB + ks*32 + bhalf*16)));
                #pragma unroll
                for (int ia = 0; ia < NP; ia++) {
                    if (ia + ib > SUM) break;
                    #pragma unroll
                    for (int mf = 0; mf < 4; mf++)
                        #pragma unroll
                        for (int nfi = 0; nfi < NF; nfi++)
                            mma16816(acc[mf][nfi], Ar[ia][mf], Br[nfi]);
                }
            }
        }
        __syncthreads();
        if (ch + 2 < NC) load_chunk(ch + 2, s);
    }

    // ================= epilogues =================
    if (EPI == 2) {
        float* sD = (float*)smem;             // [128][258]
        int*   sB = (int*)(smem + 133120);    // [128]
        float* sW = (float*)(smem + 133696);  // [16]

        // phase 1: all 256 approx distances per row -> smem
        #pragma unroll
        for (int mf = 0; mf < 4; mf++)
            #pragma unroll
            for (int h = 0; h < 2; h++) {
                int rowl = mw*64 + mf*16 + g + 8*h;
                #pragma unroll
                for (int nfi = 0; nfi < NF; nfi++) {
                    int c0 = nw*WN + nfi*8 + 2*tq;
                    sD[rowl*258 + c0]     = cbnS[c0]     - 2.f*acc[mf][nfi][h*2+0];
                    sD[rowl*258 + c0 + 1] = cbnS[c0 + 1] - 2.f*acc[mf][nfi][h*2+1];
                }
            }
        __syncthreads();

        // phase 2: per-row candidate-exact fp32 argmin (warp per 8 rows)
        for (int r8 = 0; r8 < 8; r8++) {
            int rowl = wid*8 + r8;
            float* drow = sD + rowl*258;
            float bv = FLT_MAX;
            #pragma unroll
            for (int k0 = 0; k0 < KC_; k0 += 32) bv = fminf(bv, drow[k0 + lane]);
            #pragma unroll
            for (int o = 16; o; o >>= 1) bv = fminf(bv, __shfl_xor_sync(0xffffffffu, bv, o));
            const float thr = bv + EPS_CAND;
            const float* rrow = gR + (size_t)(m0 + rowl)*H_;
            float ebv = FLT_MAX; int ebi = KC_;
            #pragma unroll
            for (int k0 = 0; k0 < KC_; k0 += 32) {
                unsigned mask = __ballot_sync(0xffffffffu, drow[k0 + lane] <= thr);
                while (mask) {
                    int j = __ffs(mask) - 1; mask &= mask - 1;
                    int k = k0 + j;
                    const float* cv = cbf + ((size_t)q*KC_ + k)*H_;
                    float s = 0.f;
                    #pragma unroll 4
                    for (int t = lane; t < H_; t += 32) s = fmaf(rrow[t], cv[t], s);
                    #pragma unroll
                    for (int o = 16; o; o >>= 1) s += __shfl_down_sync(0xffffffffu, s, o);
                    s = __shfl_sync(0xffffffffu, s, 0);
                    float de = cbnS[k] - 2.f*s;
                    if (de < ebv) { ebv = de; ebi = k; }   // ascending k + strict '<' = earliest min
                }
            }
            if (lane == 0) sB[rowl] = ebi;
        }
        __syncthreads();

        if (wq && tid < 128)
            idx_out[(size_t)(m0 + tid) * Q_ + q] = (float)sB[tid];

        // residual update: warp w handles rows w*8..w*8+7
        float csw = 0.f;
        for (int r8 = 0; r8 < 8; r8++) {
            int rowl = wid*8 + r8;
            int bi = sB[rowl];
            size_t gr = (size_t)(m0 + rowl);
            const float2* cb2 = (const float2*)(cbf + ((size_t)q*KC_ + bi)*H_);
            float2* R2 = (float2*)(gR + gr*H_);
            float cs = 0.f;
            for (int i = lane; i < H_/2; i += 32) {
                float2 r = R2[i], c = cb2[i];
                float2 rn = { r.x - c.x, r.y - c.y };
                cs += rn.x*rn.x + rn.y*rn.y;
                if (!last) {
                    R2[i] = rn;
                    *(uint32_t*)&gRc[0][gr*H_ + 2*i] =
                        bfpack(__bfloat162float(__float2bfloat16_rn(rn.x)),
                               __bfloat162float(__float2bfloat16_rn(rn.y)));
                } else {
                    float2 z = ((const float2*)(gZ + gr*H_))[i];
                    float q0 = z.x - rn.x, q1 = z.y - rn.y;
                    float h0, m0f, h1, m1f;
                    split2s(q0, h0, m0f); split2s(q1, h1, m1f);
                    *(uint32_t*)&gQc[0][gr*H_ + 2*i] = bfpack(h0, h1);
                    *(uint32_t*)&gQc[1][gr*H_ + 2*i] = bfpack(m0f, m1f);
                }
            }
            #pragma unroll
            for (int o = 16; o; o >>= 1) cs += __shfl_down_sync(0xffffffffu, cs, o);
            if (lane == 0) csw += cs;
        }
        if (lane == 0) sW[wid] = csw;
        __syncthreads();
        if (tid == 0) {
            float t = 0.f;
            #pragma unroll
            for (int i = 0; i < 16; i++) t += sW[i];
            g_commit[q*512 + blockIdx.x] = t;
        }
    } else {
        const int NOUT = (EPI == 4) ? E_ : H_;
        float lsum = 0.f;
        #pragma unroll
        for (int mf = 0; mf < 4; mf++)
            #pragma unroll
            for (int h = 0; h < 2; h++) {
                int row = m0 + mw*64 + mf*16 + g + 8*h;
                #pragma unroll
                for (int nfi = 0; nfi < NF; nfi++) {
                    int col = n0 + nw*WN + nfi*8 + 2*tq;
                    float v0 = acc[mf][nfi][h*2+0] + __ldg(bias + col);
                    float v1 = acc[mf][nfi][h*2+1] + __ldg(bias + col + 1);
                    if (EPI == 3) { v0 = fmaxf(v0, 0.f); v1 = fmaxf(v1, 0.f); }
                    size_t go = (size_t)row*NOUT + col;
                    if (EPI == 4) {
                        out[go] = v0; out[go+1] = v1;
                        float d0 = v0 - __ldg(xref + go);
                        float d1 = v1 - __ldg(xref + go + 1);
                        lsum = fmaf(d0, d0, fmaf(d1, d1, lsum));
                    } else {
                        float h0, mm0, h1, mm1;
                        split2s(v0, h0, mm0); split2s(v1, h1, mm1);
                        *(uint32_t*)&gGc[0][go] = bfpack(h0, h1);
                        *(uint32_t*)&gGc[1][go] = bfpack(mm0, mm1);
                    }
                }
            }
        if (EPI == 4) {
            float* sW = (float*)smem;
            #pragma unroll
            for (int o = 16; o; o >>= 1) lsum += __shfl_down_sync(0xffffffffu, lsum, o);
            if (lane == 0) sW[wid] = lsum;
            __syncthreads();
            if (tid == 0) {
                float t = 0.f;
                #pragma unroll
                for (int i = 0; i < 16; i++) t += sW[i];
                g_recon[blockIdx.y*512 + blockIdx.x] = t;
            }
        }
    }
}

// ---------------- final scalar reduction ----------------
__global__ void finalize_kernel(float* __restrict__ out) {
    __shared__ double sc[256], sr[256];
    double c = 0.0, r = 0.0;
    for (int i = threadIdx.x; i < Q_*512; i += 256) c += (double)g_commit[i];
    for (int i = threadIdx.x; i < 3*512; i += 256) r += (double)g_recon[i];
    sc[threadIdx.x] = c; sr[threadIdx.x] = r;
    __syncthreads();
    for (int s = 128; s; s >>= 1) {
        if (threadIdx.x < s) { sc[threadIdx.x] += sc[threadIdx.x+s]; sr[threadIdx.x] += sr[threadIdx.x+s]; }
        __syncthreads();
    }
    if (threadIdx.x == 0) {
        out[(size_t)B_*E_ + (size_t)B_*Q_ + 0] = (float)(sr[0] / ((double)B_ * (double)E_));
        out[(size_t)B_*E_ + (size_t)B_*Q_ + 1] = (float)(0.25 * sc[0] / ((double)B_ * (double)H_));
    }
}

// ---------------- launch ----------------
extern "C" void kernel_launch(void* const* d_in, const int* in_sizes, int n_in,
                              void* d_out, int out_size) {
    const float* x   = (const float*)d_in[0];
    const float* We1 = (const float*)d_in[1];
    const float* be1 = (const float*)d_in[2];
    const float* We2 = (const float*)d_in[3];
    const float* be2 = (const float*)d_in[4];
    const float* Wd1 = (const float*)d_in[5];
    const float* bd1 = (const float*)d_in[6];
    const float* Wd2 = (const float*)d_in[7];
    const float* bd2 = (const float*)d_in[8];
    const float* cb  = (const float*)d_in[9];
    float* out = (float*)d_out;

    const int full = out_size >= (int)((size_t)B_*E_ + (size_t)B_*Q_ + 2);
    float* idxo = out + (size_t)B_*E_;

    const int S_DEC = 2*2*(128*128 + 128*128);   // 131072 (NT=128, KCH=64, NP=2)
    const int S_SC  = 134144;                    // sD(132096)+cbn+sB+sW; staging (49152) overlaps sD

    cudaFuncSetAttribute(tc<2,256,32,0>, cudaFuncAttributeMaxDynamicSharedMemorySize, S_SC);
    cudaFuncSetAttribute(tc<3,128,64,1>, cudaFuncAttributeMaxDynamicSharedMemorySize, S_DEC);
    cudaFuncSetAttribute(tc<4,128,64,1>, cudaFuncAttributeMaxDynamicSharedMemorySize, S_DEC);

    prep_weights<<<1024, 256>>>(Wd1, Wd2, cb);
    cbnorm_kernel<<<(Q_*KC_)/8, 256>>>(cb);

    // encoder: fp32 SIMT (proven-accurate z), double-buffered + vector LDS
    genc<true, 0><<<dim3(H_/128, B_/128), 256>>>(x, We1, be1, B_, H_, E_);
    genc<false,1><<<dim3(H_/128, B_/128), 256>>>(nullptr, We2, be2, B_, H_, H_);

    // residual VQ: 1-term tensor scores + candidate-exact fp32 argmin + fused residual update
    for (int q = 0; q < Q_; q++)
        tc<2,256,32,0><<<dim3(512,1), 512, S_SC>>>(H_, nullptr, q, cb, idxo, full, q == Q_-1, nullptr, nullptr);

    // decoder: tensor 3-term
    tc<3,128,64,1><<<dim3(512,4), 512, S_DEC>>>(H_, bd1, 0, nullptr, nullptr, 0, 0, nullptr, nullptr);
    tc<4,128,64,1><<<dim3(512,3), 512, S_DEC>>>(H_, bd2, 0, nullptr, nullptr, 0, 0, out, x);
    if (full) finalize_kernel<<<1, 256>>>(out);
}